// round 5
// baseline (speedup 1.0000x reference)
#include <cuda_runtime.h>
#include <math.h>
#include <stdint.h>

#define B_      2
#define T_      2048
#define D_      2048
#define NH_     8
#define NKV_    4
#define HD_     256
#define SC_     2048
#define WIN_    512
#define SOFTCAP 50.0f
#define NEGINF  -2.3819763e38f

// ---------------- scratch (device globals; no allocation allowed) ------------
__device__ float g_q[(size_t)B_*T_*NH_*HD_];
__device__ float g_k[(size_t)B_*T_*NKV_*HD_];
__device__ float g_v[(size_t)B_*T_*NKV_*HD_];
__device__ float g_kc[(size_t)B_*SC_*NKV_*HD_];
__device__ float g_vc[(size_t)B_*SC_*NKV_*HD_];
__device__ float g_attn[(size_t)B_*T_*NH_*HD_];
__device__ float2 g_rope[(size_t)SC_*128];
// pre-rounded (tf32) copies of GEMM operands
__device__ float g_xr [(size_t)B_*T_*D_];
__device__ float g_wqr[(size_t)D_*NH_*HD_];
__device__ float g_wkr[(size_t)D_*NKV_*HD_];
__device__ float g_wvr[(size_t)D_*NKV_*HD_];
__device__ float g_wor[(size_t)NH_*HD_*D_];

// ---------------- tf32 helpers -------------------------------------------------
__device__ __forceinline__ uint32_t f32_to_tf32(float x) {
    uint32_t y;
    asm("cvt.rna.tf32.f32 %0, %1;" : "=r"(y) : "f"(x));
    return y;
}
__device__ __forceinline__ float round_tf32f(float x) {
    return __uint_as_float(f32_to_tf32(x));
}
__device__ __forceinline__ void tf32split(float x, float& hi, float& lo) {
    hi = round_tf32f(x);
    lo = round_tf32f(x - hi);
}

__device__ __forceinline__ void mma_tf32(float& d0, float& d1, float& d2, float& d3,
                                         uint32_t a0, uint32_t a1, uint32_t a2, uint32_t a3,
                                         uint32_t b0, uint32_t b1) {
    asm volatile("mma.sync.aligned.m16n8k8.row.col.f32.tf32.tf32.f32 "
                 "{%0,%1,%2,%3}, {%4,%5,%6,%7}, {%8,%9}, {%0,%1,%2,%3};"
                 : "+f"(d0), "+f"(d1), "+f"(d2), "+f"(d3)
                 : "r"(a0), "r"(a1), "r"(a2), "r"(a3), "r"(b0), "r"(b1));
}

__device__ __forceinline__ void cpasync16(uint32_t saddr, const void* gptr) {
    asm volatile("cp.async.cg.shared.global [%0], [%1], 16;\n" :: "r"(saddr), "l"(gptr));
}
__device__ __forceinline__ void cpasync_commit() { asm volatile("cp.async.commit_group;"); }
__device__ __forceinline__ void cpasync_wait0()  { asm volatile("cp.async.wait_group 0;"); }
__device__ __forceinline__ void cpasync_wait1()  { asm volatile("cp.async.wait_group 1;"); }

// fast math (NaN-safe for our ranges)
__device__ __forceinline__ float fast_tanh(float x) {
    float xc = fminf(fmaxf(x, -15.0f), 15.0f);
    float e = __expf(-2.0f * xc);
    return (1.0f - e) / (1.0f + e);
}

// ---------------- tf32 round pass -----------------------------------------------
__global__ void round_pass(const float* __restrict__ in, float* __restrict__ out, int n4)
{
    const int i = blockIdx.x * 256 + threadIdx.x;
    if (i < n4) {
        float4 v = ((const float4*)in)[i];
        v.x = round_tf32f(v.x); v.y = round_tf32f(v.y);
        v.z = round_tf32f(v.z); v.w = round_tf32f(v.w);
        ((float4*)out)[i] = v;
    }
}

// ---------------- tf32 tensor-core GEMM (BK=32, pre-rounded inputs) -------------
#define AS_STRIDE 36    // 32 + 4 pad
#define BS_STRIDE 136   // 128 + 8 pad
#define AS_ELEMS  (128 * AS_STRIDE)
#define BS_ELEMS  (32 * BS_STRIDE)
#define GEMM_SMEM ((2 * AS_ELEMS + 2 * BS_ELEMS) * 4)

__device__ __forceinline__ void gemm_body(const float* __restrict__ A,
                                          const float* __restrict__ W,
                                          float* __restrict__ C,
                                          int M, int N, int K,
                                          int row0, int col0)
{
    extern __shared__ float dynsmem[];
    float* Asm = dynsmem;                       // [2][AS_ELEMS]
    float* Bsm = dynsmem + 2 * AS_ELEMS;        // [2][BS_ELEMS]

    const int tid  = threadIdx.x;
    const int warp = tid >> 5;
    const int lane = tid & 31;
    const int warpM = warp >> 2;
    const int warpN = warp & 3;
    const int gid = lane >> 2;
    const int tig = lane & 3;

    uint32_t sA = (uint32_t)__cvta_generic_to_shared(Asm);
    uint32_t sB = (uint32_t)__cvta_generic_to_shared(Bsm);
    const uint32_t sAbuf = AS_ELEMS * 4;
    const uint32_t sBbuf = BS_ELEMS * 4;

    const int ntiles = K / 32;

    auto load_tile = [&](int kt, int buf) {
#pragma unroll
        for (int i = 0; i < 4; i++) {
            const int fi = tid + i * 256;            // 1024 float4 over 128x32
            const int r = fi >> 3, c4 = (fi & 7) * 4;
            cpasync16(sA + buf * sAbuf + (r * AS_STRIDE + c4) * 4,
                      A + (size_t)(row0 + r) * K + kt * 32 + c4);
        }
#pragma unroll
        for (int i = 0; i < 4; i++) {
            const int fi = tid + i * 256;            // 1024 float4 over 32x128
            const int r = fi >> 5, c4 = (fi & 31) * 4;
            cpasync16(sB + buf * sBbuf + (r * BS_STRIDE + c4) * 4,
                      W + (size_t)(kt * 32 + r) * N + col0 + c4);
        }
    };

    float acc[4][4][4];
#pragma unroll
    for (int i = 0; i < 4; i++)
#pragma unroll
        for (int j = 0; j < 4; j++)
#pragma unroll
            for (int r = 0; r < 4; r++) acc[i][j][r] = 0.0f;

    load_tile(0, 0);
    cpasync_commit();

    for (int kt = 0; kt < ntiles; kt++) {
        const int buf = kt & 1;
        if (kt + 1 < ntiles) {
            load_tile(kt + 1, buf ^ 1);
            cpasync_commit();
            cpasync_wait1();
        } else {
            cpasync_wait0();
        }
        __syncthreads();

        const float* Ab = Asm + buf * AS_ELEMS;
        const float* Bb = Bsm + buf * BS_ELEMS;

#pragma unroll
        for (int ks = 0; ks < 4; ks++) {
            const int kb = ks * 8;
            uint32_t af[4][4], bf[4][2];
#pragma unroll
            for (int mt = 0; mt < 4; mt++) {
                const int rbase = warpM * 64 + mt * 16;
                af[mt][0] = __float_as_uint(Ab[(rbase + gid)     * AS_STRIDE + kb + tig]);
                af[mt][1] = __float_as_uint(Ab[(rbase + gid + 8) * AS_STRIDE + kb + tig]);
                af[mt][2] = __float_as_uint(Ab[(rbase + gid)     * AS_STRIDE + kb + tig + 4]);
                af[mt][3] = __float_as_uint(Ab[(rbase + gid + 8) * AS_STRIDE + kb + tig + 4]);
            }
#pragma unroll
            for (int nt = 0; nt < 4; nt++) {
                const int cb = warpN * 32 + nt * 8 + gid;
                bf[nt][0] = __float_as_uint(Bb[(kb + tig)     * BS_STRIDE + cb]);
                bf[nt][1] = __float_as_uint(Bb[(kb + tig + 4) * BS_STRIDE + cb]);
            }
#pragma unroll
            for (int mt = 0; mt < 4; mt++)
#pragma unroll
                for (int nt = 0; nt < 4; nt++)
                    mma_tf32(acc[mt][nt][0], acc[mt][nt][1], acc[mt][nt][2], acc[mt][nt][3],
                             af[mt][0], af[mt][1], af[mt][2], af[mt][3],
                             bf[nt][0], bf[nt][1]);
        }
        __syncthreads();
    }

#pragma unroll
    for (int mt = 0; mt < 4; mt++) {
        const int r = row0 + warpM * 64 + mt * 16 + gid;
#pragma unroll
        for (int nt = 0; nt < 4; nt++) {
            const int c = col0 + warpN * 32 + nt * 8 + tig * 2;
            *(float2*)(C + (size_t)r * N + c)       = make_float2(acc[mt][nt][0], acc[mt][nt][1]);
            *(float2*)(C + (size_t)(r + 8) * N + c) = make_float2(acc[mt][nt][2], acc[mt][nt][3]);
        }
    }
}

__global__ void __launch_bounds__(256) gemm_tf32(const float* __restrict__ A,
                                                 const float* __restrict__ W,
                                                 float* __restrict__ C,
                                                 int M, int N, int K)
{
    gemm_body(A, W, C, M, N, K, blockIdx.y * 128, blockIdx.x * 128);
}

// K and V projections fused into one launch (z picks operand set)
__global__ void __launch_bounds__(256) gemm_tf32_kv(const float* __restrict__ A,
                                                    const float* __restrict__ W0,
                                                    const float* __restrict__ W1,
                                                    float* __restrict__ C0,
                                                    float* __restrict__ C1,
                                                    int M, int N, int K)
{
    const float* W = blockIdx.z ? W1 : W0;
    float*       C = blockIdx.z ? C1 : C0;
    gemm_body(A, W, C, M, N, K, blockIdx.y * 128, blockIdx.x * 128);
}

// ---------------- rope table ----------------------------------------------------
__global__ void rope_table_kernel()
{
    const int idx = blockIdx.x * 256 + threadIdx.x;
    const int pos = idx >> 7;
    const int i   = idx & 127;
    const double ts  = pow(10000.0, (double)i / 128.0);
    const double ang = (double)pos / ts;
    double sn, cs;
    sincos(ang, &sn, &cs);
    g_rope[idx] = make_float2((float)cs, (float)sn);
}

// ---------------- cache merge (V pre-rounded to tf32) ----------------------------
__global__ void merge_cache(const float* __restrict__ kcache,
                            const float* __restrict__ vcache,
                            const int* __restrict__ cur)
{
    const int idx = blockIdx.x * 256 + threadIdx.x;
    const int per_b = SC_ * NKV_ * HD_;
    const int b = idx / per_b;
    const int rem = idx - b * per_b;
    const int s = rem / (NKV_ * HD_);
    const int c = rem - s * (NKV_ * HD_);
    const int ci = *cur;
    const int t = s - ci;
    g_kc[idx] = kcache[idx];
    const float vv = (t >= 0 && t < T_) ? g_v[((size_t)b * T_ + t) * (NKV_ * HD_) + c]
                                        : vcache[idx];
    g_vc[idx] = round_tf32f(vv);
}

// ---------------- RMSNorm + RoPE ---------------------------------------------------
__global__ void normrope_kernel(const float* __restrict__ in,
                                float* __restrict__ out,
                                const float* __restrict__ scale,
                                const int* __restrict__ seg,
                                const int* __restrict__ cur,
                                int heads, int to_cache)
{
    const int bt = blockIdx.x;
    const int h  = blockIdx.y;
    const int d  = threadIdx.x;

    const float v = in[((size_t)bt * heads + h) * HD_ + d];

    float ss = v * v;
#pragma unroll
    for (int o = 16; o; o >>= 1) ss += __shfl_xor_sync(0xffffffffu, ss, o);
    __shared__ float red[8];
    __shared__ float s_ms;
    __shared__ float sh[HD_];
    const int lane = d & 31, w = d >> 5;
    if (lane == 0) red[w] = ss;
    __syncthreads();
    if (d == 0) {
        float t = 0.0f;
#pragma unroll
        for (int i = 0; i < 8; i++) t += red[i];
        s_ms = rsqrtf(t / (float)HD_ + 1e-6f);
    }
    __syncthreads();

    const float n = v * s_ms * (1.0f + scale[d]);
    sh[d] = n;
    __syncthreads();

    int pos = seg[bt];
    if (pos < 0) pos = 0;
    if (pos > SC_ - 1) pos = SC_ - 1;
    const int i = d & 127;
    const float2 cssn = g_rope[pos * 128 + i];
    const float x1 = sh[i], x2 = sh[i + 128];
    const float r = (d < 128) ? (x1 * cssn.x - x2 * cssn.y)
                              : (x2 * cssn.x + x1 * cssn.y);

    if (to_cache) {
        const int b = bt / T_, t = bt - b * T_;
        const int slot = *cur + t;
        if (slot < SC_)
            out[(((size_t)b * SC_ + slot) * heads + h) * HD_ + d] = r;
    } else {
        out[((size_t)bt * heads + h) * HD_ + d] = r;
    }
}

// ---------------- tensor-core flash attention --------------------------------------
#define QKS 260
#define VSS 264
#define SSS 36

struct AttnSmem {
    float Qhi[32 * QKS];
    float Qlo[32 * QKS];
    float Khi[32 * QKS];
    float Klo[32 * QKS];
    float Vs [32 * VSS];
    float Ss [32 * SSS];
    float m[32], l[32], al[32];
    int   pos[32];
    int   srange[2];
};

__global__ void __launch_bounds__(256) attn_mma(const int* __restrict__ seg)
{
    extern __shared__ char smem_raw[];
    AttnSmem& sm = *reinterpret_cast<AttnSmem*>(smem_raw);

    const int tid  = threadIdx.x;
    const int warp = tid >> 5;
    const int lane = tid & 31;
    const int gid  = lane >> 2;
    const int tig  = lane & 3;
    const int warpM = warp >> 2;
    const int warpN = warp & 3;

    const int q0 = blockIdx.x * 32;
    const int h  = blockIdx.y;
    const int b  = blockIdx.z;
    const int kvh = h / (NH_ / NKV_);

    const float* qbase = g_q + (((size_t)b * T_ + q0) * NH_ + h) * HD_;
    const float qscale = 0.0625f;
#pragma unroll
    for (int j = 0; j < 8; j++) {
        const int fi = tid + j * 256;
        const int r = fi >> 6, c4 = (fi & 63) * 4;
        float4 v = *(const float4*)(qbase + (size_t)r * NH_ * HD_ + c4);
        float hv, lv;
        tf32split(v.x * qscale, hv, lv); sm.Qhi[r*QKS+c4+0]=hv; sm.Qlo[r*QKS+c4+0]=lv;
        tf32split(v.y * qscale, hv, lv); sm.Qhi[r*QKS+c4+1]=hv; sm.Qlo[r*QKS+c4+1]=lv;
        tf32split(v.z * qscale, hv, lv); sm.Qhi[r*QKS+c4+2]=hv; sm.Qlo[r*QKS+c4+2]=lv;
        tf32split(v.w * qscale, hv, lv); sm.Qhi[r*QKS+c4+3]=hv; sm.Qlo[r*QKS+c4+3]=lv;
    }
    if (tid < 32) {
        sm.m[tid] = -1e30f;
        sm.l[tid] = 0.0f;
        sm.pos[tid] = seg[b * T_ + q0 + tid];
    }
    __syncthreads();
    if (tid == 0) {
        int mn = sm.pos[0], mx = sm.pos[0];
        for (int j = 1; j < 32; j++) { mn = min(mn, sm.pos[j]); mx = max(mx, sm.pos[j]); }
        int lo = mn - (WIN_ - 1); if (lo < 0) lo = 0;
        int hi = mx; if (hi > SC_ - 1) hi = SC_ - 1;
        sm.srange[0] = lo & ~31;
        sm.srange[1] = hi;
    }
    __syncthreads();
    const int s_lo = sm.srange[0], s_hi = sm.srange[1];

    const int arow = warpM * 16 + gid;

    float o[8][4];
#pragma unroll
    for (int nf = 0; nf < 8; nf++)
#pragma unroll
        for (int r = 0; r < 4; r++) o[nf][r] = 0.0f;

    const float* kbase = g_kc + ((size_t)b * SC_ * NKV_ + kvh) * HD_;
    const float* vbase = g_vc + ((size_t)b * SC_ * NKV_ + kvh) * HD_;

    for (int s0 = s_lo; s0 <= s_hi; s0 += 32) {
#pragma unroll
        for (int j = 0; j < 8; j++) {
            const int fi = tid + j * 256;
            const int r = fi >> 6, c4 = (fi & 63) * 4;
            const int s = s0 + r;
            float4 kv = make_float4(0.f,0.f,0.f,0.f), vv = kv;
            if (s < SC_) {
                kv = *(const float4*)(kbase + (size_t)s * NKV_ * HD_ + c4);
                vv = *(const float4*)(vbase + (size_t)s * NKV_ * HD_ + c4);
            }
            float hv, lv;
            tf32split(kv.x, hv, lv); sm.Khi[r*QKS+c4+0]=hv; sm.Klo[r*QKS+c4+0]=lv;
            tf32split(kv.y, hv, lv); sm.Khi[r*QKS+c4+1]=hv; sm.Klo[r*QKS+c4+1]=lv;
            tf32split(kv.z, hv, lv); sm.Khi[r*QKS+c4+2]=hv; sm.Klo[r*QKS+c4+2]=lv;
            tf32split(kv.w, hv, lv); sm.Khi[r*QKS+c4+3]=hv; sm.Klo[r*QKS+c4+3]=lv;
            // V is pre-rounded to tf32 at merge_cache
            *(float4*)&sm.Vs[r*VSS+c4] = vv;
        }
        __syncthreads();

        float sc0 = 0.f, sc1 = 0.f, sc2 = 0.f, sc3 = 0.f;
        const int bcol = warpN * 8 + gid;
#pragma unroll 4
        for (int kb = 0; kb < HD_; kb += 8) {
            const uint32_t ah0 = __float_as_uint(sm.Qhi[(arow)    *QKS + kb + tig]);
            const uint32_t ah1 = __float_as_uint(sm.Qhi[(arow + 8)*QKS + kb + tig]);
            const uint32_t ah2 = __float_as_uint(sm.Qhi[(arow)    *QKS + kb + tig + 4]);
            const uint32_t ah3 = __float_as_uint(sm.Qhi[(arow + 8)*QKS + kb + tig + 4]);
            const uint32_t al0 = __float_as_uint(sm.Qlo[(arow)    *QKS + kb + tig]);
            const uint32_t al1 = __float_as_uint(sm.Qlo[(arow + 8)*QKS + kb + tig]);
            const uint32_t al2 = __float_as_uint(sm.Qlo[(arow)    *QKS + kb + tig + 4]);
            const uint32_t al3 = __float_as_uint(sm.Qlo[(arow + 8)*QKS + kb + tig + 4]);
            const uint32_t bh0 = __float_as_uint(sm.Khi[bcol*QKS + kb + tig]);
            const uint32_t bh1 = __float_as_uint(sm.Khi[bcol*QKS + kb + tig + 4]);
            const uint32_t bl0 = __float_as_uint(sm.Klo[bcol*QKS + kb + tig]);
            const uint32_t bl1 = __float_as_uint(sm.Klo[bcol*QKS + kb + tig + 4]);
            mma_tf32(sc0, sc1, sc2, sc3, ah0, ah1, ah2, ah3, bh0, bh1);
            mma_tf32(sc0, sc1, sc2, sc3, al0, al1, al2, al3, bh0, bh1);
            mma_tf32(sc0, sc1, sc2, sc3, ah0, ah1, ah2, ah3, bl0, bl1);
        }

        {
            const int c0 = warpN * 8 + tig * 2;
            const int sa = s0 + c0, sb2 = s0 + c0 + 1;
            const int qp0 = sm.pos[arow], qp1 = sm.pos[arow + 8];
            const float v0 = SOFTCAP * fast_tanh(sc0 * (1.0f / SOFTCAP));
            const float v1 = SOFTCAP * fast_tanh(sc1 * (1.0f / SOFTCAP));
            const float v2 = SOFTCAP * fast_tanh(sc2 * (1.0f / SOFTCAP));
            const float v3 = SOFTCAP * fast_tanh(sc3 * (1.0f / SOFTCAP));
            sm.Ss[(arow)    *SSS + c0    ] = (sa  <= qp0 && qp0 - sa  < WIN_ && sa  < SC_) ? v0 : NEGINF;
            sm.Ss[(arow)    *SSS + c0 + 1] = (sb2 <= qp0 && qp0 - sb2 < WIN_ && sb2 < SC_) ? v1 : NEGINF;
            sm.Ss[(arow + 8)*SSS + c0    ] = (sa  <= qp1 && qp1 - sa  < WIN_ && sa  < SC_) ? v2 : NEGINF;
            sm.Ss[(arow + 8)*SSS + c0 + 1] = (sb2 <= qp1 && qp1 - sb2 < WIN_ && sb2 < SC_) ? v3 : NEGINF;
        }
        __syncthreads();

        {
            const int r = tid >> 3, sub = tid & 7;
            float* srow = &sm.Ss[r * SSS + sub * 4];
            float mx = fmaxf(fmaxf(srow[0], srow[1]), fmaxf(srow[2], srow[3]));
#pragma unroll
            for (int off = 1; off < 8; off <<= 1)
                mx = fmaxf(mx, __shfl_xor_sync(0xffffffffu, mx, off));
            const float mo = sm.m[r];
            const float mn = fmaxf(mo, mx);
            const float a  = __expf(mo - mn);
            float ls = 0.0f;
#pragma unroll
            for (int i = 0; i < 4; i++) {
                const float p = __expf(srow[i] - mn);
                srow[i] = round_tf32f(p);
                ls += p;
            }
#pragma unroll
            for (int off = 1; off < 8; off <<= 1)
                ls += __shfl_xor_sync(0xffffffffu, ls, off);
            if (sub == 0) {
                sm.m[r] = mn;
                sm.l[r] = sm.l[r] * a + ls;
                sm.al[r] = a;
            }
        }
        __syncthreads();

        {
            const float a0 = sm.al[arow], a1 = sm.al[arow + 8];
#pragma unroll
            for (int nf = 0; nf < 8; nf++) {
                o[nf][0] *= a0; o[nf][1] *= a0;
                o[nf][2] *= a1; o[nf][3] *= a1;
            }
#pragma unroll
            for (int kb = 0; kb < 32; kb += 8) {
                const uint32_t pa0 = __float_as_uint(sm.Ss[(arow)    *SSS + kb + tig]);
                const uint32_t pa1 = __float_as_uint(sm.Ss[(arow + 8)*SSS + kb + tig]);
                const uint32_t pa2 = __float_as_uint(sm.Ss[(arow)    *SSS + kb + tig + 4]);
                const uint32_t pa3 = __float_as_uint(sm.Ss[(arow + 8)*SSS + kb + tig + 4]);
#pragma unroll
                for (int nf = 0; nf < 8; nf++) {
                    const int col = warpN * 64 + nf * 8 + gid;
                    const uint32_t b0 = __float_as_uint(sm.Vs[(kb + tig)    *VSS + col]);
                    const uint32_t b1 = __float_as_uint(sm.Vs[(kb + tig + 4)*VSS + col]);
                    mma_tf32(o[nf][0], o[nf][1], o[nf][2], o[nf][3],
                             pa0, pa1, pa2, pa3, b0, b1);
                }
            }
        }
        __syncthreads();
    }

    // epilogue: O / l, rounded to tf32 (feeds the wo GEMM A operand)
    const float li0 = 1.0f / sm.l[arow];
    const float li1 = 1.0f / sm.l[arow + 8];
    const int row0g = q0 + arow;
#pragma unroll
    for (int nf = 0; nf < 8; nf++) {
        const int col = warpN * 64 + nf * 8 + tig * 2;
        float* p0 = g_attn + (((size_t)b * T_ + row0g)     * NH_ + h) * HD_ + col;
        float* p1 = g_attn + (((size_t)b * T_ + row0g + 8) * NH_ + h) * HD_ + col;
        *(float2*)p0 = make_float2(round_tf32f(o[nf][0] * li0), round_tf32f(o[nf][1] * li0));
        *(float2*)p1 = make_float2(round_tf32f(o[nf][2] * li1), round_tf32f(o[nf][3] * li1));
    }
}

// ---------------- launcher ------------------------------------------------------
extern "C" void kernel_launch(void* const* d_in, const int* in_sizes, int n_in,
                              void* d_out, int out_size)
{
    const float* x      = (const float*)d_in[0];
    const int*   seg    = (const int*)  d_in[1];
    const int*   cur    = (const int*)  d_in[2];
    const float* wq     = (const float*)d_in[3];
    const float* wk     = (const float*)d_in[4];
    const float* wv     = (const float*)d_in[5];
    const float* wo     = (const float*)d_in[6];
    const float* qns    = (const float*)d_in[7];
    const float* kns    = (const float*)d_in[8];
    const float* kcache = (const float*)d_in[9];
    const float* vcache = (const float*)d_in[10];
    float* out = (float*)d_out;

    float *qp, *kp, *vp, *attnp, *kcp;
    float *xr, *wqr, *wkr, *wvr, *wor;
    cudaGetSymbolAddress((void**)&qp,    g_q);
    cudaGetSymbolAddress((void**)&kp,    g_k);
    cudaGetSymbolAddress((void**)&vp,    g_v);
    cudaGetSymbolAddress((void**)&attnp, g_attn);
    cudaGetSymbolAddress((void**)&kcp,   g_kc);
    cudaGetSymbolAddress((void**)&xr,    g_xr);
    cudaGetSymbolAddress((void**)&wqr,   g_wqr);
    cudaGetSymbolAddress((void**)&wkr,   g_wkr);
    cudaGetSymbolAddress((void**)&wvr,   g_wvr);
    cudaGetSymbolAddress((void**)&wor,   g_wor);

    const int M = B_ * T_;

    // pre-round GEMM operands to tf32
    {
        const int nx = (B_*T_*D_) / 4,   nq = (D_*NH_*HD_) / 4;
        const int nk = (D_*NKV_*HD_) / 4;
        round_pass<<<(nx + 255)/256, 256>>>(x,  xr,  nx);
        round_pass<<<(nq + 255)/256, 256>>>(wq, wqr, nq);
        round_pass<<<(nk + 255)/256, 256>>>(wk, wkr, nk);
        round_pass<<<(nk + 255)/256, 256>>>(wv, wvr, nk);
        round_pass<<<(nq + 255)/256, 256>>>(wo, wor, nq);
    }

    rope_table_kernel<<<(SC_ * 128) / 256, 256>>>();

    cudaFuncSetAttribute(gemm_tf32,    cudaFuncAttributeMaxDynamicSharedMemorySize, GEMM_SMEM);
    cudaFuncSetAttribute(gemm_tf32_kv, cudaFuncAttributeMaxDynamicSharedMemorySize, GEMM_SMEM);

    gemm_tf32<<<dim3((NH_*HD_)/128, M/128), 256, GEMM_SMEM>>>(xr, wqr, qp, M, NH_*HD_, D_);
    gemm_tf32_kv<<<dim3((NKV_*HD_)/128, M/128, 2), 256, GEMM_SMEM>>>(
        xr, wkr, wvr, kp, vp, M, NKV_*HD_, D_);

    merge_cache<<<(B_*SC_*NKV_*HD_)/256, 256>>>(kcache, vcache, cur);

    normrope_kernel<<<dim3(M, NH_),  256>>>(qp, qp,  qns, seg, cur, NH_,  0);
    normrope_kernel<<<dim3(M, NKV_), 256>>>(kp, kcp, kns, seg, cur, NKV_, 1);

    cudaFuncSetAttribute(attn_mma, cudaFuncAttributeMaxDynamicSharedMemorySize,
                         (int)sizeof(AttnSmem));
    attn_mma<<<dim3(T_/32, NH_, B_), 256, sizeof(AttnSmem)>>>(seg);

    gemm_tf32<<<dim3(D_/128, M/128), 256, GEMM_SMEM>>>(attnp, wor, out, M, D_, D_);
}

// round 6
// speedup vs baseline: 1.0099x; 1.0099x over previous
#include <cuda_runtime.h>
#include <math.h>
#include <stdint.h>

#define B_      2
#define T_      2048
#define D_      2048
#define NH_     8
#define NKV_    4
#define HD_     256
#define SC_     2048
#define WIN_    512
#define SOFTCAP 50.0f
#define NEGINF  -2.3819763e38f

// ---------------- scratch (device globals; no allocation allowed) ------------
__device__ float g_q[(size_t)B_*T_*NH_*HD_];
__device__ float g_k[(size_t)B_*T_*NKV_*HD_];
__device__ float g_v[(size_t)B_*T_*NKV_*HD_];
__device__ float g_kc[(size_t)B_*SC_*NKV_*HD_];
__device__ float g_vc[(size_t)B_*SC_*NKV_*HD_];
__device__ float g_attn[(size_t)B_*T_*NH_*HD_];   // k-permuted within 16-blocks
__device__ float2 g_rope[(size_t)SC_*128];
// pre-rounded tf32, k-permuted operands
__device__ float g_xr [(size_t)B_*T_*D_];          // [M][K] perm16(k)
__device__ float g_wqt[(size_t)(NH_*HD_)*D_];      // [N][K] perm16(k)
__device__ float g_wkt[(size_t)(NKV_*HD_)*D_];
__device__ float g_wvt[(size_t)(NKV_*HD_)*D_];
__device__ float g_wot[(size_t)D_*(NH_*HD_)];

// ---------------- tf32 helpers -------------------------------------------------
__device__ __forceinline__ uint32_t f32_to_tf32(float x) {
    uint32_t y;
    asm("cvt.rna.tf32.f32 %0, %1;" : "=r"(y) : "f"(x));
    return y;
}
__device__ __forceinline__ float round_tf32f(float x) {
    return __uint_as_float(f32_to_tf32(x));
}
__device__ __forceinline__ void tf32split(float x, float& hi, float& lo) {
    hi = round_tf32f(x);
    lo = round_tf32f(x - hi);
}

__device__ __forceinline__ void mma_tf32(float& d0, float& d1, float& d2, float& d3,
                                         uint32_t a0, uint32_t a1, uint32_t a2, uint32_t a3,
                                         uint32_t b0, uint32_t b1) {
    asm volatile("mma.sync.aligned.m16n8k8.row.col.f32.tf32.tf32.f32 "
                 "{%0,%1,%2,%3}, {%4,%5,%6,%7}, {%8,%9}, {%0,%1,%2,%3};"
                 : "+f"(d0), "+f"(d1), "+f"(d2), "+f"(d3)
                 : "r"(a0), "r"(a1), "r"(a2), "r"(a3), "r"(b0), "r"(b1));
}

__device__ __forceinline__ void cpasync16(uint32_t saddr, const void* gptr) {
    asm volatile("cp.async.cg.shared.global [%0], [%1], 16;\n" :: "r"(saddr), "l"(gptr));
}
__device__ __forceinline__ void cpasync_commit() { asm volatile("cp.async.commit_group;"); }
__device__ __forceinline__ void cpasync_wait0()  { asm volatile("cp.async.wait_group 0;"); }
__device__ __forceinline__ void cpasync_wait1()  { asm volatile("cp.async.wait_group 1;"); }

__device__ __forceinline__ float fast_tanh(float x) {
    float xc = fminf(fmaxf(x, -15.0f), 15.0f);
    float e = __expf(-2.0f * xc);
    return (1.0f - e) / (1.0f + e);
}

// ---------------- preprocessing: round + k16-perm -------------------------------
// perm(c) = (c&3)*4 + (c>>2) within each 16-element k block.
__global__ void xperm(const float* __restrict__ in, float* __restrict__ out, int n4)
{
    const int idx = blockIdx.x * 256 + threadIdx.x;
    if (idx < n4) {
        float4 v = ((const float4*)in)[idx];
        const int base = (idx >> 2) * 16, j = idx & 3;
        out[base + j]      = round_tf32f(v.x);
        out[base + 4 + j]  = round_tf32f(v.y);
        out[base + 8 + j]  = round_tf32f(v.z);
        out[base + 12 + j] = round_tf32f(v.w);
    }
}

// w[K][N] -> wt[N][K] rounded, k16-permuted. block (32,8), grid (N/32, K/32).
__global__ void wtrans(const float* __restrict__ w, float* __restrict__ wt, int K, int N)
{
    __shared__ float tile[32][33];
    const int n0 = blockIdx.x * 32, k0 = blockIdx.y * 32;
    const int tx = threadIdx.x, ty = threadIdx.y;
#pragma unroll
    for (int i = 0; i < 32; i += 8)
        tile[ty + i][tx] = round_tf32f(w[(size_t)(k0 + ty + i) * N + n0 + tx]);
    __syncthreads();
    const int pk = (tx & ~15) | (((tx & 3) << 2) | ((tx >> 2) & 3));
#pragma unroll
    for (int i = 0; i < 32; i += 8)
        wt[(size_t)(n0 + ty + i) * K + k0 + pk] = tile[tx][ty + i];
}

// ---------------- tf32 GEMM v3: LDS.128 fragments --------------------------------
// C[M,N] = A[M,K] @ W[K,N]; A is [M][K] perm16; Bt is [N][K] perm16.
// Block 128x128, BK=16, 8 warps (2Mx4N, warp tile 64x32), double buffer.
__device__ __forceinline__ void gemm3_body(const float* __restrict__ A,
                                           const float* __restrict__ Bt,
                                           float* __restrict__ C,
                                           int M, int N, int K,
                                           int row0, int col0)
{
    __shared__ float As[2][128 * 16];
    __shared__ float Bs[2][128 * 16];

    const int tid  = threadIdx.x;
    const int warp = tid >> 5;
    const int lane = tid & 31;
    const int warpM = warp >> 2;
    const int warpN = warp & 3;
    const int gid = lane >> 2;
    const int tig = lane & 3;

    uint32_t sA = (uint32_t)__cvta_generic_to_shared(&As[0][0]);
    uint32_t sB = (uint32_t)__cvta_generic_to_shared(&Bs[0][0]);
    const uint32_t bufbytes = 128 * 16 * 4;

    const int ntiles = K / 16;

    auto load_tile = [&](int kt, int buf) {
#pragma unroll
        for (int i = 0; i < 2; i++) {
            const int ch = tid + i * 256;              // 512 chunks of 16B
            const int r = ch >> 2, c4 = (ch & 3) * 4;
            cpasync16(sA + buf * bufbytes + (r * 16 + c4) * 4,
                      A + (size_t)(row0 + r) * K + kt * 16 + c4);
            cpasync16(sB + buf * bufbytes + (r * 16 + c4) * 4,
                      Bt + (size_t)(col0 + r) * K + kt * 16 + c4);
        }
    };

    float acc[4][4][4];
#pragma unroll
    for (int i = 0; i < 4; i++)
#pragma unroll
        for (int j = 0; j < 4; j++)
#pragma unroll
            for (int r = 0; r < 4; r++) acc[i][j][r] = 0.0f;

    load_tile(0, 0);
    cpasync_commit();

    for (int kt = 0; kt < ntiles; kt++) {
        const int buf = kt & 1;
        if (kt + 1 < ntiles) {
            load_tile(kt + 1, buf ^ 1);
            cpasync_commit();
            cpasync_wait1();
        } else {
            cpasync_wait0();
        }
        __syncthreads();

        const float* Ab = &As[buf][0];
        const float* Bb = &Bs[buf][0];

        // B fragments: one float4 per nt (covers both k8 sub-steps)
        float4 b4[4];
#pragma unroll
        for (int nt = 0; nt < 4; nt++)
            b4[nt] = *(const float4*)&Bb[(warpN * 32 + nt * 8 + gid) * 16 + tig * 4];

#pragma unroll
        for (int mt = 0; mt < 4; mt++) {
            const int r0 = warpM * 64 + mt * 16 + gid;
            const float4 a0 = *(const float4*)&Ab[r0 * 16 + tig * 4];
            const float4 a1 = *(const float4*)&Ab[(r0 + 8) * 16 + tig * 4];
#pragma unroll
            for (int nt = 0; nt < 4; nt++) {
                // k8 step 0: A k-elems {tig, tig+4} = (x, y); B = (x, y)
                mma_tf32(acc[mt][nt][0], acc[mt][nt][1], acc[mt][nt][2], acc[mt][nt][3],
                         __float_as_uint(a0.x), __float_as_uint(a1.x),
                         __float_as_uint(a0.y), __float_as_uint(a1.y),
                         __float_as_uint(b4[nt].x), __float_as_uint(b4[nt].y));
                // k8 step 1: elems {8+tig, 8+tig+4} = (z, w)
                mma_tf32(acc[mt][nt][0], acc[mt][nt][1], acc[mt][nt][2], acc[mt][nt][3],
                         __float_as_uint(a0.z), __float_as_uint(a1.z),
                         __float_as_uint(a0.w), __float_as_uint(a1.w),
                         __float_as_uint(b4[nt].z), __float_as_uint(b4[nt].w));
            }
        }
        __syncthreads();
    }

#pragma unroll
    for (int mt = 0; mt < 4; mt++) {
        const int r = row0 + warpM * 64 + mt * 16 + gid;
#pragma unroll
        for (int nt = 0; nt < 4; nt++) {
            const int c = col0 + warpN * 32 + nt * 8 + tig * 2;
            *(float2*)(C + (size_t)r * N + c)       = make_float2(acc[mt][nt][0], acc[mt][nt][1]);
            *(float2*)(C + (size_t)(r + 8) * N + c) = make_float2(acc[mt][nt][2], acc[mt][nt][3]);
        }
    }
}

__global__ void __launch_bounds__(256, 2) gemm3(const float* __restrict__ A,
                                                const float* __restrict__ Bt,
                                                float* __restrict__ C,
                                                int M, int N, int K)
{
    gemm3_body(A, Bt, C, M, N, K, blockIdx.y * 128, blockIdx.x * 128);
}

__global__ void __launch_bounds__(256, 2) gemm3_kv(const float* __restrict__ A,
                                                   const float* __restrict__ B0,
                                                   const float* __restrict__ B1,
                                                   float* __restrict__ C0,
                                                   float* __restrict__ C1,
                                                   int M, int N, int K)
{
    const float* Bt = blockIdx.z ? B1 : B0;
    float*       C  = blockIdx.z ? C1 : C0;
    gemm3_body(A, Bt, C, M, N, K, blockIdx.y * 128, blockIdx.x * 128);
}

// ---------------- rope table ----------------------------------------------------
__global__ void rope_table_kernel()
{
    const int idx = blockIdx.x * 256 + threadIdx.x;
    const int pos = idx >> 7;
    const int i   = idx & 127;
    const double ts  = pow(10000.0, (double)i / 128.0);
    const double ang = (double)pos / ts;
    double sn, cs;
    sincos(ang, &sn, &cs);
    g_rope[idx] = make_float2((float)cs, (float)sn);
}

// ---------------- cache merge (V pre-rounded to tf32) -----------------------------
__global__ void merge_cache(const float* __restrict__ kcache,
                            const float* __restrict__ vcache,
                            const int* __restrict__ cur)
{
    const int idx = blockIdx.x * 256 + threadIdx.x;
    const int per_b = SC_ * NKV_ * HD_;
    const int b = idx / per_b;
    const int rem = idx - b * per_b;
    const int s = rem / (NKV_ * HD_);
    const int c = rem - s * (NKV_ * HD_);
    const int ci = *cur;
    const int t = s - ci;
    g_kc[idx] = kcache[idx];
    const float vv = (t >= 0 && t < T_) ? g_v[((size_t)b * T_ + t) * (NKV_ * HD_) + c]
                                        : vcache[idx];
    g_vc[idx] = round_tf32f(vv);
}

// ---------------- RMSNorm + RoPE ---------------------------------------------------
__global__ void normrope_kernel(const float* __restrict__ in,
                                float* __restrict__ out,
                                const float* __restrict__ scale,
                                const int* __restrict__ seg,
                                const int* __restrict__ cur,
                                int heads, int to_cache)
{
    const int bt = blockIdx.x;
    const int h  = blockIdx.y;
    const int d  = threadIdx.x;

    const float v = in[((size_t)bt * heads + h) * HD_ + d];

    float ss = v * v;
#pragma unroll
    for (int o = 16; o; o >>= 1) ss += __shfl_xor_sync(0xffffffffu, ss, o);
    __shared__ float red[8];
    __shared__ float s_ms;
    __shared__ float sh[HD_];
    const int lane = d & 31, w = d >> 5;
    if (lane == 0) red[w] = ss;
    __syncthreads();
    if (d == 0) {
        float t = 0.0f;
#pragma unroll
        for (int i = 0; i < 8; i++) t += red[i];
        s_ms = rsqrtf(t / (float)HD_ + 1e-6f);
    }
    __syncthreads();

    const float n = v * s_ms * (1.0f + scale[d]);
    sh[d] = n;
    __syncthreads();

    int pos = seg[bt];
    if (pos < 0) pos = 0;
    if (pos > SC_ - 1) pos = SC_ - 1;
    const int i = d & 127;
    const float2 cssn = g_rope[pos * 128 + i];
    const float x1 = sh[i], x2 = sh[i + 128];
    const float r = (d < 128) ? (x1 * cssn.x - x2 * cssn.y)
                              : (x2 * cssn.x + x1 * cssn.y);

    if (to_cache) {
        const int b = bt / T_, t = bt - b * T_;
        const int slot = *cur + t;
        if (slot < SC_)
            out[(((size_t)b * SC_ + slot) * heads + h) * HD_ + d] = r;
    } else {
        out[((size_t)bt * heads + h) * HD_ + d] = r;
    }
}

// ---------------- tensor-core flash attention --------------------------------------
#define QKS 260
#define VSS 264
#define SSS 36

struct AttnSmem {
    float Qhi[32 * QKS];
    float Qlo[32 * QKS];
    float Khi[32 * QKS];
    float Klo[32 * QKS];
    float Vs [32 * VSS];
    float Ss [32 * SSS];
    float m[32], l[32], al[32];
    int   pos[32];
    int   srange[2];
};

__global__ void __launch_bounds__(256) attn_mma(const int* __restrict__ seg)
{
    extern __shared__ char smem_raw[];
    AttnSmem& sm = *reinterpret_cast<AttnSmem*>(smem_raw);

    const int tid  = threadIdx.x;
    const int warp = tid >> 5;
    const int lane = tid & 31;
    const int gid  = lane >> 2;
    const int tig  = lane & 3;
    const int warpM = warp >> 2;
    const int warpN = warp & 3;

    const int q0 = blockIdx.x * 32;
    const int h  = blockIdx.y;
    const int b  = blockIdx.z;
    const int kvh = h / (NH_ / NKV_);

    const float* qbase = g_q + (((size_t)b * T_ + q0) * NH_ + h) * HD_;
    const float qscale = 0.0625f;
#pragma unroll
    for (int j = 0; j < 8; j++) {
        const int fi = tid + j * 256;
        const int r = fi >> 6, c4 = (fi & 63) * 4;
        float4 v = *(const float4*)(qbase + (size_t)r * NH_ * HD_ + c4);
        float hv, lv;
        tf32split(v.x * qscale, hv, lv); sm.Qhi[r*QKS+c4+0]=hv; sm.Qlo[r*QKS+c4+0]=lv;
        tf32split(v.y * qscale, hv, lv); sm.Qhi[r*QKS+c4+1]=hv; sm.Qlo[r*QKS+c4+1]=lv;
        tf32split(v.z * qscale, hv, lv); sm.Qhi[r*QKS+c4+2]=hv; sm.Qlo[r*QKS+c4+2]=lv;
        tf32split(v.w * qscale, hv, lv); sm.Qhi[r*QKS+c4+3]=hv; sm.Qlo[r*QKS+c4+3]=lv;
    }
    if (tid < 32) {
        sm.m[tid] = -1e30f;
        sm.l[tid] = 0.0f;
        sm.pos[tid] = seg[b * T_ + q0 + tid];
    }
    __syncthreads();
    if (tid == 0) {
        int mn = sm.pos[0], mx = sm.pos[0];
        for (int j = 1; j < 32; j++) { mn = min(mn, sm.pos[j]); mx = max(mx, sm.pos[j]); }
        int lo = mn - (WIN_ - 1); if (lo < 0) lo = 0;
        int hi = mx; if (hi > SC_ - 1) hi = SC_ - 1;
        sm.srange[0] = lo & ~31;
        sm.srange[1] = hi;
    }
    __syncthreads();
    const int s_lo = sm.srange[0], s_hi = sm.srange[1];

    const int arow = warpM * 16 + gid;

    float o[8][4];
#pragma unroll
    for (int nf = 0; nf < 8; nf++)
#pragma unroll
        for (int r = 0; r < 4; r++) o[nf][r] = 0.0f;

    const float* kbase = g_kc + ((size_t)b * SC_ * NKV_ + kvh) * HD_;
    const float* vbase = g_vc + ((size_t)b * SC_ * NKV_ + kvh) * HD_;

    for (int s0 = s_lo; s0 <= s_hi; s0 += 32) {
#pragma unroll
        for (int j = 0; j < 8; j++) {
            const int fi = tid + j * 256;
            const int r = fi >> 6, c4 = (fi & 63) * 4;
            const int s = s0 + r;
            float4 kv = make_float4(0.f,0.f,0.f,0.f), vv = kv;
            if (s < SC_) {
                kv = *(const float4*)(kbase + (size_t)s * NKV_ * HD_ + c4);
                vv = *(const float4*)(vbase + (size_t)s * NKV_ * HD_ + c4);
            }
            float hv, lv;
            tf32split(kv.x, hv, lv); sm.Khi[r*QKS+c4+0]=hv; sm.Klo[r*QKS+c4+0]=lv;
            tf32split(kv.y, hv, lv); sm.Khi[r*QKS+c4+1]=hv; sm.Klo[r*QKS+c4+1]=lv;
            tf32split(kv.z, hv, lv); sm.Khi[r*QKS+c4+2]=hv; sm.Klo[r*QKS+c4+2]=lv;
            tf32split(kv.w, hv, lv); sm.Khi[r*QKS+c4+3]=hv; sm.Klo[r*QKS+c4+3]=lv;
            *(float4*)&sm.Vs[r*VSS+c4] = vv;
        }
        __syncthreads();

        float sc0 = 0.f, sc1 = 0.f, sc2 = 0.f, sc3 = 0.f;
        const int bcol = warpN * 8 + gid;
#pragma unroll 4
        for (int kb = 0; kb < HD_; kb += 8) {
            const uint32_t ah0 = __float_as_uint(sm.Qhi[(arow)    *QKS + kb + tig]);
            const uint32_t ah1 = __float_as_uint(sm.Qhi[(arow + 8)*QKS + kb + tig]);
            const uint32_t ah2 = __float_as_uint(sm.Qhi[(arow)    *QKS + kb + tig + 4]);
            const uint32_t ah3 = __float_as_uint(sm.Qhi[(arow + 8)*QKS + kb + tig + 4]);
            const uint32_t al0 = __float_as_uint(sm.Qlo[(arow)    *QKS + kb + tig]);
            const uint32_t al1 = __float_as_uint(sm.Qlo[(arow + 8)*QKS + kb + tig]);
            const uint32_t al2 = __float_as_uint(sm.Qlo[(arow)    *QKS + kb + tig + 4]);
            const uint32_t al3 = __float_as_uint(sm.Qlo[(arow + 8)*QKS + kb + tig + 4]);
            const uint32_t bh0 = __float_as_uint(sm.Khi[bcol*QKS + kb + tig]);
            const uint32_t bh1 = __float_as_uint(sm.Khi[bcol*QKS + kb + tig + 4]);
            const uint32_t bl0 = __float_as_uint(sm.Klo[bcol*QKS + kb + tig]);
            const uint32_t bl1 = __float_as_uint(sm.Klo[bcol*QKS + kb + tig + 4]);
            mma_tf32(sc0, sc1, sc2, sc3, ah0, ah1, ah2, ah3, bh0, bh1);
            mma_tf32(sc0, sc1, sc2, sc3, al0, al1, al2, al3, bh0, bh1);
            mma_tf32(sc0, sc1, sc2, sc3, ah0, ah1, ah2, ah3, bl0, bl1);
        }

        {
            const int c0 = warpN * 8 + tig * 2;
            const int sa = s0 + c0, sb2 = s0 + c0 + 1;
            const int qp0 = sm.pos[arow], qp1 = sm.pos[arow + 8];
            const float v0 = SOFTCAP * fast_tanh(sc0 * (1.0f / SOFTCAP));
            const float v1 = SOFTCAP * fast_tanh(sc1 * (1.0f / SOFTCAP));
            const float v2 = SOFTCAP * fast_tanh(sc2 * (1.0f / SOFTCAP));
            const float v3 = SOFTCAP * fast_tanh(sc3 * (1.0f / SOFTCAP));
            sm.Ss[(arow)    *SSS + c0    ] = (sa  <= qp0 && qp0 - sa  < WIN_ && sa  < SC_) ? v0 : NEGINF;
            sm.Ss[(arow)    *SSS + c0 + 1] = (sb2 <= qp0 && qp0 - sb2 < WIN_ && sb2 < SC_) ? v1 : NEGINF;
            sm.Ss[(arow + 8)*SSS + c0    ] = (sa  <= qp1 && qp1 - sa  < WIN_ && sa  < SC_) ? v2 : NEGINF;
            sm.Ss[(arow + 8)*SSS + c0 + 1] = (sb2 <= qp1 && qp1 - sb2 < WIN_ && sb2 < SC_) ? v3 : NEGINF;
        }
        __syncthreads();

        {
            const int r = tid >> 3, sub = tid & 7;
            float* srow = &sm.Ss[r * SSS + sub * 4];
            float mx = fmaxf(fmaxf(srow[0], srow[1]), fmaxf(srow[2], srow[3]));
#pragma unroll
            for (int off = 1; off < 8; off <<= 1)
                mx = fmaxf(mx, __shfl_xor_sync(0xffffffffu, mx, off));
            const float mo = sm.m[r];
            const float mn = fmaxf(mo, mx);
            const float a  = __expf(mo - mn);
            float ls = 0.0f;
#pragma unroll
            for (int i = 0; i < 4; i++) {
                const float p = __expf(srow[i] - mn);
                srow[i] = round_tf32f(p);
                ls += p;
            }
#pragma unroll
            for (int off = 1; off < 8; off <<= 1)
                ls += __shfl_xor_sync(0xffffffffu, ls, off);
            if (sub == 0) {
                sm.m[r] = mn;
                sm.l[r] = sm.l[r] * a + ls;
                sm.al[r] = a;
            }
        }
        __syncthreads();

        {
            const float a0 = sm.al[arow], a1 = sm.al[arow + 8];
#pragma unroll
            for (int nf = 0; nf < 8; nf++) {
                o[nf][0] *= a0; o[nf][1] *= a0;
                o[nf][2] *= a1; o[nf][3] *= a1;
            }
#pragma unroll
            for (int kb = 0; kb < 32; kb += 8) {
                const uint32_t pa0 = __float_as_uint(sm.Ss[(arow)    *SSS + kb + tig]);
                const uint32_t pa1 = __float_as_uint(sm.Ss[(arow + 8)*SSS + kb + tig]);
                const uint32_t pa2 = __float_as_uint(sm.Ss[(arow)    *SSS + kb + tig + 4]);
                const uint32_t pa3 = __float_as_uint(sm.Ss[(arow + 8)*SSS + kb + tig + 4]);
#pragma unroll
                for (int nf = 0; nf < 8; nf++) {
                    const int col = warpN * 64 + nf * 8 + gid;
                    const uint32_t b0 = __float_as_uint(sm.Vs[(kb + tig)    *VSS + col]);
                    const uint32_t b1 = __float_as_uint(sm.Vs[(kb + tig + 4)*VSS + col]);
                    mma_tf32(o[nf][0], o[nf][1], o[nf][2], o[nf][3],
                             pa0, pa1, pa2, pa3, b0, b1);
                }
            }
        }
        __syncthreads();
    }

    // epilogue: O / l, tf32-rounded, written k16-PERMUTED (feeds o-proj A operand)
    const float li0 = 1.0f / sm.l[arow];
    const float li1 = 1.0f / sm.l[arow + 8];
    const int row0g = q0 + arow;
    float* base0 = g_attn + (((size_t)b * T_ + row0g)     * NH_ + h) * HD_;
    float* base1 = g_attn + (((size_t)b * T_ + row0g + 8) * NH_ + h) * HD_;
#pragma unroll
    for (int nf = 0; nf < 8; nf++) {
        const int c = warpN * 64 + nf * 8 + tig * 2;
        const int c1 = c + 1;
        const int pc  = (c  & ~15) | (((c  & 3) << 2) | ((c  >> 2) & 3));
        const int pc1 = (c1 & ~15) | (((c1 & 3) << 2) | ((c1 >> 2) & 3));
        base0[pc]  = round_tf32f(o[nf][0] * li0);
        base0[pc1] = round_tf32f(o[nf][1] * li0);
        base1[pc]  = round_tf32f(o[nf][2] * li1);
        base1[pc1] = round_tf32f(o[nf][3] * li1);
    }
}

// ---------------- launcher ------------------------------------------------------
extern "C" void kernel_launch(void* const* d_in, const int* in_sizes, int n_in,
                              void* d_out, int out_size)
{
    const float* x      = (const float*)d_in[0];
    const int*   seg    = (const int*)  d_in[1];
    const int*   cur    = (const int*)  d_in[2];
    const float* wq     = (const float*)d_in[3];
    const float* wk     = (const float*)d_in[4];
    const float* wv     = (const float*)d_in[5];
    const float* wo     = (const float*)d_in[6];
    const float* qns    = (const float*)d_in[7];
    const float* kns    = (const float*)d_in[8];
    const float* kcache = (const float*)d_in[9];
    const float* vcache = (const float*)d_in[10];
    float* out = (float*)d_out;

    float *qp, *kp, *vp, *attnp, *kcp;
    float *xr, *wqt, *wkt, *wvt, *wot;
    cudaGetSymbolAddress((void**)&qp,    g_q);
    cudaGetSymbolAddress((void**)&kp,    g_k);
    cudaGetSymbolAddress((void**)&vp,    g_v);
    cudaGetSymbolAddress((void**)&attnp, g_attn);
    cudaGetSymbolAddress((void**)&kcp,   g_kc);
    cudaGetSymbolAddress((void**)&xr,    g_xr);
    cudaGetSymbolAddress((void**)&wqt,   g_wqt);
    cudaGetSymbolAddress((void**)&wkt,   g_wkt);
    cudaGetSymbolAddress((void**)&wvt,   g_wvt);
    cudaGetSymbolAddress((void**)&wot,   g_wot);

    const int M = B_ * T_;

    // preprocessing: round + perm x; round + transpose + perm weights
    xperm<<<((B_*T_*D_/4) + 255)/256, 256>>>(x, xr, B_*T_*D_/4);
    wtrans<<<dim3((NH_*HD_)/32,  D_/32), dim3(32,8)>>>(wq, wqt, D_, NH_*HD_);
    wtrans<<<dim3((NKV_*HD_)/32, D_/32), dim3(32,8)>>>(wk, wkt, D_, NKV_*HD_);
    wtrans<<<dim3((NKV_*HD_)/32, D_/32), dim3(32,8)>>>(wv, wvt, D_, NKV_*HD_);
    wtrans<<<dim3(D_/32, (NH_*HD_)/32), dim3(32,8)>>>(wo, wot, NH_*HD_, D_);

    rope_table_kernel<<<(SC_ * 128) / 256, 256>>>();

    gemm3<<<dim3((NH_*HD_)/128, M/128), 256>>>(xr, wqt, qp, M, NH_*HD_, D_);
    gemm3_kv<<<dim3((NKV_*HD_)/128, M/128, 2), 256>>>(xr, wkt, wvt, kp, vp, M, NKV_*HD_, D_);

    merge_cache<<<(B_*SC_*NKV_*HD_)/256, 256>>>(kcache, vcache, cur);

    normrope_kernel<<<dim3(M, NH_),  256>>>(qp, qp,  qns, seg, cur, NH_,  0);
    normrope_kernel<<<dim3(M, NKV_), 256>>>(kp, kcp, kns, seg, cur, NKV_, 1);

    cudaFuncSetAttribute(attn_mma, cudaFuncAttributeMaxDynamicSharedMemorySize,
                         (int)sizeof(AttnSmem));
    attn_mma<<<dim3(T_/32, NH_, B_), 256, sizeof(AttnSmem)>>>(seg);

    gemm3<<<dim3(D_/128, M/128), 256>>>(attnp, wot, out, M, D_, NH_*HD_);
}

// round 8
// speedup vs baseline: 1.0559x; 1.0455x over previous
#include <cuda_runtime.h>
#include <math.h>
#include <stdint.h>

#define B_      2
#define T_      2048
#define D_      2048
#define NH_     8
#define NKV_    4
#define HD_     256
#define SC_     2048
#define WIN_    512
#define SOFTCAP 50.0f
#define NEGINF  -2.3819763e38f
#define QKVW    4096       // fused qkv row width

// ---------------- scratch (device globals; no allocation allowed) ------------
__device__ float g_qkv[(size_t)B_*T_*QKVW];        // q | k | v fused, 67 MB
__device__ float g_wcat[(size_t)D_*QKVW];          // wq | wk | wv fused
__device__ float g_kc[(size_t)B_*SC_*NKV_*HD_];
__device__ float g_vc[(size_t)B_*SC_*NKV_*HD_];
__device__ float g_attn[(size_t)B_*T_*NH_*HD_];
__device__ float2 g_rope[(size_t)SC_*128];

// ---------------- tf32 helpers -------------------------------------------------
__device__ __forceinline__ uint32_t f32_to_tf32(float x) {
    uint32_t y;
    asm("cvt.rna.tf32.f32 %0, %1;" : "=r"(y) : "f"(x));
    return y;
}
__device__ __forceinline__ float round_tf32f(float x) {
    return __uint_as_float(f32_to_tf32(x));
}
__device__ __forceinline__ void tf32split(float x, float& hi, float& lo) {
    hi = round_tf32f(x);
    lo = round_tf32f(x - hi);
}

__device__ __forceinline__ void mma_tf32(float& d0, float& d1, float& d2, float& d3,
                                         uint32_t a0, uint32_t a1, uint32_t a2, uint32_t a3,
                                         uint32_t b0, uint32_t b1) {
    asm volatile("mma.sync.aligned.m16n8k8.row.col.f32.tf32.tf32.f32 "
                 "{%0,%1,%2,%3}, {%4,%5,%6,%7}, {%8,%9}, {%0,%1,%2,%3};"
                 : "+f"(d0), "+f"(d1), "+f"(d2), "+f"(d3)
                 : "r"(a0), "r"(a1), "r"(a2), "r"(a3), "r"(b0), "r"(b1));
}

__device__ __forceinline__ void cpasync16(uint32_t saddr, const void* gptr) {
    asm volatile("cp.async.cg.shared.global [%0], [%1], 16;\n" :: "r"(saddr), "l"(gptr));
}
__device__ __forceinline__ void cpasync_commit() { asm volatile("cp.async.commit_group;"); }
__device__ __forceinline__ void cpasync_wait0()  { asm volatile("cp.async.wait_group 0;"); }
__device__ __forceinline__ void cpasync_wait1()  { asm volatile("cp.async.wait_group 1;"); }

__device__ __forceinline__ float fast_tanh(float x) {
    float xc = fminf(fmaxf(x, -15.0f), 15.0f);
    float e = __expf(-2.0f * xc);
    return (1.0f - e) / (1.0f + e);
}

// ---------------- weight concat: wq|wk|wv -> [D][4096] ---------------------------
__global__ void wcat_kernel(const float* __restrict__ wq,
                            const float* __restrict__ wk,
                            const float* __restrict__ wv)
{
    const int i4 = blockIdx.x * 256 + threadIdx.x;        // float4 index
    const int total4 = D_ * QKVW / 4;
    if (i4 >= total4) return;
    const int k = i4 / (QKVW / 4);
    const int n4 = i4 - k * (QKVW / 4);
    const int n = n4 * 4;
    float4 v;
    if (n < 2048)       v = *(const float4*)(wq + (size_t)k * 2048 + n);
    else if (n < 3072)  v = *(const float4*)(wk + (size_t)k * 1024 + (n - 2048));
    else                v = *(const float4*)(wv + (size_t)k * 1024 + (n - 3072));
    *(float4*)(g_wcat + (size_t)k * QKVW + n) = v;
}

// ---------------- tf32 GEMM: 3-stage cp.async, one sync per k-iter ---------------
#define AS_STRIDE 20
#define BS_STRIDE 136
#define AE (128 * AS_STRIDE)
#define BE (16 * BS_STRIDE)
#define GSMEM (3 * (AE + BE) * 4)

__global__ void __launch_bounds__(256) gemm_tf32(const float* __restrict__ A,
                                                 const float* __restrict__ W,
                                                 float* __restrict__ C,
                                                 int M, int N, int K)
{
    extern __shared__ float dyn[];
    float* Asm = dyn;              // [3][AE]
    float* Bsm = dyn + 3 * AE;     // [3][BE]

    const int tid  = threadIdx.x;
    const int warp = tid >> 5;
    const int lane = tid & 31;
    const int warpM = warp >> 2;
    const int warpN = warp & 3;
    const int gid = lane >> 2;
    const int tig = lane & 3;

    const int row0 = blockIdx.y * 128;
    const int col0 = blockIdx.x * 128;

    const int a_r  = tid >> 2;            // 0..63 (rows a_r, a_r+64)
    const int a_c4 = (tid & 3) * 4;
    const int b_r  = tid >> 5;            // 0..7 (rows b_r, b_r+8)
    const int b_c4 = (tid & 31) * 4;

    uint32_t sA = (uint32_t)__cvta_generic_to_shared(Asm);
    uint32_t sB = (uint32_t)__cvta_generic_to_shared(Bsm);

    const int ntiles = K / 16;

    auto load_tile = [&](int kt, int st) {
        cpasync16(sA + (st * AE + a_r * AS_STRIDE + a_c4) * 4,
                  A + (size_t)(row0 + a_r) * K + kt * 16 + a_c4);
        cpasync16(sA + (st * AE + (a_r + 64) * AS_STRIDE + a_c4) * 4,
                  A + (size_t)(row0 + a_r + 64) * K + kt * 16 + a_c4);
        cpasync16(sB + (st * BE + b_r * BS_STRIDE + b_c4) * 4,
                  W + (size_t)(kt * 16 + b_r) * N + col0 + b_c4);
        cpasync16(sB + (st * BE + (b_r + 8) * BS_STRIDE + b_c4) * 4,
                  W + (size_t)(kt * 16 + b_r + 8) * N + col0 + b_c4);
    };

    float acc[4][4][4];
#pragma unroll
    for (int i = 0; i < 4; i++)
#pragma unroll
        for (int j = 0; j < 4; j++)
#pragma unroll
            for (int r = 0; r < 4; r++) acc[i][j][r] = 0.0f;

    load_tile(0, 0);
    cpasync_commit();
    load_tile(1, 1);
    cpasync_commit();

    for (int kt = 0; kt < ntiles; kt++) {
        const int st = kt % 3;
        if (kt + 1 < ntiles) cpasync_wait1(); else cpasync_wait0();
        __syncthreads();

        const float* Ab = Asm + st * AE;
        const float* Bb = Bsm + st * BE;

#pragma unroll
        for (int ks = 0; ks < 2; ks++) {
            const int kb = ks * 8;
            uint32_t af[4][4], bf[4][2];
#pragma unroll
            for (int mt = 0; mt < 4; mt++) {
                const int rbase = warpM * 64 + mt * 16;
                af[mt][0] = f32_to_tf32(Ab[(rbase + gid)     * AS_STRIDE + kb + tig]);
                af[mt][1] = f32_to_tf32(Ab[(rbase + gid + 8) * AS_STRIDE + kb + tig]);
                af[mt][2] = f32_to_tf32(Ab[(rbase + gid)     * AS_STRIDE + kb + tig + 4]);
                af[mt][3] = f32_to_tf32(Ab[(rbase + gid + 8) * AS_STRIDE + kb + tig + 4]);
            }
#pragma unroll
            for (int nt = 0; nt < 4; nt++) {
                const int cb = warpN * 32 + nt * 8 + gid;
                bf[nt][0] = f32_to_tf32(Bb[(kb + tig)     * BS_STRIDE + cb]);
                bf[nt][1] = f32_to_tf32(Bb[(kb + tig + 4) * BS_STRIDE + cb]);
            }
#pragma unroll
            for (int mt = 0; mt < 4; mt++)
#pragma unroll
                for (int nt = 0; nt < 4; nt++)
                    mma_tf32(acc[mt][nt][0], acc[mt][nt][1], acc[mt][nt][2], acc[mt][nt][3],
                             af[mt][0], af[mt][1], af[mt][2], af[mt][3],
                             bf[nt][0], bf[nt][1]);
        }

        if (kt + 2 < ntiles) {
            load_tile(kt + 2, (kt + 2) % 3);
            cpasync_commit();
        }
    }

#pragma unroll
    for (int mt = 0; mt < 4; mt++) {
        const int r = row0 + warpM * 64 + mt * 16 + gid;
#pragma unroll
        for (int nt = 0; nt < 4; nt++) {
            const int c = col0 + warpN * 32 + nt * 8 + tig * 2;
            *(float2*)(C + (size_t)r * N + c)       = make_float2(acc[mt][nt][0], acc[mt][nt][1]);
            *(float2*)(C + (size_t)(r + 8) * N + c) = make_float2(acc[mt][nt][2], acc[mt][nt][3]);
        }
    }
}

// ---------------- rope table ----------------------------------------------------
__global__ void rope_table_kernel()
{
    const int idx = blockIdx.x * 256 + threadIdx.x;
    const int pos = idx >> 7;
    const int i   = idx & 127;
    const double ts  = pow(10000.0, (double)i / 128.0);
    const double ang = (double)pos / ts;
    double sn, cs;
    sincos(ang, &sn, &cs);
    g_rope[idx] = make_float2((float)cs, (float)sn);
}

// ---------------- cache merge (V from fused qkv, pre-rounded) --------------------
__global__ void merge_cache(const float* __restrict__ kcache,
                            const float* __restrict__ vcache,
                            const int* __restrict__ cur)
{
    const int idx = blockIdx.x * 256 + threadIdx.x;
    const int per_b = SC_ * NKV_ * HD_;
    const int b = idx / per_b;
    const int rem = idx - b * per_b;
    const int s = rem / (NKV_ * HD_);
    const int c = rem - s * (NKV_ * HD_);
    const int ci = *cur;
    const int t = s - ci;
    g_kc[idx] = kcache[idx];
    const float vv = (t >= 0 && t < T_)
        ? g_qkv[((size_t)b * T_ + t) * QKVW + 3072 + c]
        : vcache[idx];
    g_vc[idx] = round_tf32f(vv);
}

// ---------------- RMSNorm + RoPE (reads fused qkv) --------------------------------
__global__ void normrope_kernel(const float* __restrict__ qkv,
                                float* __restrict__ out,
                                const float* __restrict__ scale,
                                const int* __restrict__ seg,
                                const int* __restrict__ cur,
                                int heads, int in_off, int to_cache)
{
    const int bt = blockIdx.x;
    const int h  = blockIdx.y;
    const int d  = threadIdx.x;

    const size_t in_idx = (size_t)bt * QKVW + in_off + h * HD_ + d;
    const float v = qkv[in_idx];

    float ss = v * v;
#pragma unroll
    for (int o = 16; o; o >>= 1) ss += __shfl_xor_sync(0xffffffffu, ss, o);
    __shared__ float red[8];
    __shared__ float s_ms;
    __shared__ float sh[HD_];
    const int lane = d & 31, w = d >> 5;
    if (lane == 0) red[w] = ss;
    __syncthreads();
    if (d == 0) {
        float t = 0.0f;
#pragma unroll
        for (int i = 0; i < 8; i++) t += red[i];
        s_ms = rsqrtf(t / (float)HD_ + 1e-6f);
    }
    __syncthreads();

    const float n = v * s_ms * (1.0f + scale[d]);
    sh[d] = n;
    __syncthreads();

    int pos = seg[bt];
    if (pos < 0) pos = 0;
    if (pos > SC_ - 1) pos = SC_ - 1;
    const int i = d & 127;
    const float2 cssn = g_rope[pos * 128 + i];
    const float x1 = sh[i], x2 = sh[i + 128];
    const float r = (d < 128) ? (x1 * cssn.x - x2 * cssn.y)
                              : (x2 * cssn.x + x1 * cssn.y);

    if (to_cache) {
        const int b = bt / T_, t = bt - b * T_;
        const int slot = *cur + t;
        if (slot < SC_)
            out[(((size_t)b * SC_ + slot) * heads + h) * HD_ + d] = r;
    } else {
        out[in_idx] = r;   // in-place on q region
    }
}

// ---------------- tensor-core flash attention --------------------------------------
#define QKS 260
#define VSS 264
#define SSS 36

struct AttnSmem {
    float Qhi[32 * QKS];
    float Qlo[32 * QKS];
    float Khi[32 * QKS];
    float Klo[32 * QKS];
    float Vs [32 * VSS];
    float Ss [32 * SSS];
    float m[32], l[32], al[32];
    int   pos[32];
    int   srange[2];
};

__global__ void __launch_bounds__(256) attn_mma(const int* __restrict__ seg)
{
    extern __shared__ char smem_raw[];
    AttnSmem& sm = *reinterpret_cast<AttnSmem*>(smem_raw);

    const int tid  = threadIdx.x;
    const int warp = tid >> 5;
    const int lane = tid & 31;
    const int gid  = lane >> 2;
    const int tig  = lane & 3;
    const int warpM = warp >> 2;
    const int warpN = warp & 3;

    const int q0 = blockIdx.x * 32;
    const int h  = blockIdx.y;
    const int b  = blockIdx.z;
    const int kvh = h / (NH_ / NKV_);

    // Q from fused qkv (row stride QKVW)
    const float* qbase = g_qkv + ((size_t)b * T_ + q0) * QKVW + h * HD_;
    const float qscale = 0.0625f;
#pragma unroll
    for (int j = 0; j < 8; j++) {
        const int fi = tid + j * 256;
        const int r = fi >> 6, c4 = (fi & 63) * 4;
        float4 v = *(const float4*)(qbase + (size_t)r * QKVW + c4);
        float hv, lv;
        tf32split(v.x * qscale, hv, lv); sm.Qhi[r*QKS+c4+0]=hv; sm.Qlo[r*QKS+c4+0]=lv;
        tf32split(v.y * qscale, hv, lv); sm.Qhi[r*QKS+c4+1]=hv; sm.Qlo[r*QKS+c4+1]=lv;
        tf32split(v.z * qscale, hv, lv); sm.Qhi[r*QKS+c4+2]=hv; sm.Qlo[r*QKS+c4+2]=lv;
        tf32split(v.w * qscale, hv, lv); sm.Qhi[r*QKS+c4+3]=hv; sm.Qlo[r*QKS+c4+3]=lv;
    }
    if (tid < 32) {
        sm.m[tid] = -1e30f;
        sm.l[tid] = 0.0f;
        sm.pos[tid] = seg[b * T_ + q0 + tid];
    }
    __syncthreads();
    if (tid == 0) {
        int mn = sm.pos[0], mx = sm.pos[0];
        for (int j = 1; j < 32; j++) { mn = min(mn, sm.pos[j]); mx = max(mx, sm.pos[j]); }
        int lo = mn - (WIN_ - 1); if (lo < 0) lo = 0;
        int hi = mx; if (hi > SC_ - 1) hi = SC_ - 1;
        sm.srange[0] = lo & ~31;
        sm.srange[1] = hi;
    }
    __syncthreads();
    const int s_lo = sm.srange[0], s_hi = sm.srange[1];

    const int arow = warpM * 16 + gid;

    float o[8][4];
#pragma unroll
    for (int nf = 0; nf < 8; nf++)
#pragma unroll
        for (int r = 0; r < 4; r++) o[nf][r] = 0.0f;

    const float* kbase = g_kc + ((size_t)b * SC_ * NKV_ + kvh) * HD_;
    const float* vbase = g_vc + ((size_t)b * SC_ * NKV_ + kvh) * HD_;

    for (int s0 = s_lo; s0 <= s_hi; s0 += 32) {
#pragma unroll
        for (int j = 0; j < 8; j++) {
            const int fi = tid + j * 256;
            const int r = fi >> 6, c4 = (fi & 63) * 4;
            const int s = s0 + r;
            float4 kv = make_float4(0.f,0.f,0.f,0.f), vv = kv;
            if (s < SC_) {
                kv = *(const float4*)(kbase + (size_t)s * NKV_ * HD_ + c4);
                vv = *(const float4*)(vbase + (size_t)s * NKV_ * HD_ + c4);
            }
            float hv, lv;
            tf32split(kv.x, hv, lv); sm.Khi[r*QKS+c4+0]=hv; sm.Klo[r*QKS+c4+0]=lv;
            tf32split(kv.y, hv, lv); sm.Khi[r*QKS+c4+1]=hv; sm.Klo[r*QKS+c4+1]=lv;
            tf32split(kv.z, hv, lv); sm.Khi[r*QKS+c4+2]=hv; sm.Klo[r*QKS+c4+2]=lv;
            tf32split(kv.w, hv, lv); sm.Khi[r*QKS+c4+3]=hv; sm.Klo[r*QKS+c4+3]=lv;
            *(float4*)&sm.Vs[r*VSS+c4] = vv;   // V pre-rounded at merge_cache
        }
        __syncthreads();

        float sc0 = 0.f, sc1 = 0.f, sc2 = 0.f, sc3 = 0.f;
        const int bcol = warpN * 8 + gid;
#pragma unroll 4
        for (int kb = 0; kb < HD_; kb += 8) {
            const uint32_t ah0 = __float_as_uint(sm.Qhi[(arow)    *QKS + kb + tig]);
            const uint32_t ah1 = __float_as_uint(sm.Qhi[(arow + 8)*QKS + kb + tig]);
            const uint32_t ah2 = __float_as_uint(sm.Qhi[(arow)    *QKS + kb + tig + 4]);
            const uint32_t ah3 = __float_as_uint(sm.Qhi[(arow + 8)*QKS + kb + tig + 4]);
            const uint32_t al0 = __float_as_uint(sm.Qlo[(arow)    *QKS + kb + tig]);
            const uint32_t al1 = __float_as_uint(sm.Qlo[(arow + 8)*QKS + kb + tig]);
            const uint32_t al2 = __float_as_uint(sm.Qlo[(arow)    *QKS + kb + tig + 4]);
            const uint32_t al3 = __float_as_uint(sm.Qlo[(arow + 8)*QKS + kb + tig + 4]);
            const uint32_t bh0 = __float_as_uint(sm.Khi[bcol*QKS + kb + tig]);
            const uint32_t bh1 = __float_as_uint(sm.Khi[bcol*QKS + kb + tig + 4]);
            const uint32_t bl0 = __float_as_uint(sm.Klo[bcol*QKS + kb + tig]);
            const uint32_t bl1 = __float_as_uint(sm.Klo[bcol*QKS + kb + tig + 4]);
            mma_tf32(sc0, sc1, sc2, sc3, ah0, ah1, ah2, ah3, bh0, bh1);
            mma_tf32(sc0, sc1, sc2, sc3, al0, al1, al2, al3, bh0, bh1);
            mma_tf32(sc0, sc1, sc2, sc3, ah0, ah1, ah2, ah3, bl0, bl1);
        }

        {
            const int c0 = warpN * 8 + tig * 2;
            const int sa = s0 + c0, sb2 = s0 + c0 + 1;
            const int qp0 = sm.pos[arow], qp1 = sm.pos[arow + 8];
            const float v0 = SOFTCAP * fast_tanh(sc0 * (1.0f / SOFTCAP));
            const float v1 = SOFTCAP * fast_tanh(sc1 * (1.0f / SOFTCAP));
            const float v2 = SOFTCAP * fast_tanh(sc2 * (1.0f / SOFTCAP));
            const float v3 = SOFTCAP * fast_tanh(sc3 * (1.0f / SOFTCAP));
            sm.Ss[(arow)    *SSS + c0    ] = (sa  <= qp0 && qp0 - sa  < WIN_ && sa  < SC_) ? v0 : NEGINF;
            sm.Ss[(arow)    *SSS + c0 + 1] = (sb2 <= qp0 && qp0 - sb2 < WIN_ && sb2 < SC_) ? v1 : NEGINF;
            sm.Ss[(arow + 8)*SSS + c0    ] = (sa  <= qp1 && qp1 - sa  < WIN_ && sa  < SC_) ? v2 : NEGINF;
            sm.Ss[(arow + 8)*SSS + c0 + 1] = (sb2 <= qp1 && qp1 - sb2 < WIN_ && sb2 < SC_) ? v3 : NEGINF;
        }
        __syncthreads();

        {
            const int r = tid >> 3, sub = tid & 7;
            float* srow = &sm.Ss[r * SSS + sub * 4];
            float mx = fmaxf(fmaxf(srow[0], srow[1]), fmaxf(srow[2], srow[3]));
#pragma unroll
            for (int off = 1; off < 8; off <<= 1)
                mx = fmaxf(mx, __shfl_xor_sync(0xffffffffu, mx, off));
            const float mo = sm.m[r];
            const float mn = fmaxf(mo, mx);
            const float a  = __expf(mo - mn);
            float ls = 0.0f;
#pragma unroll
            for (int i = 0; i < 4; i++) {
                const float p = __expf(srow[i] - mn);
                srow[i] = round_tf32f(p);
                ls += p;
            }
#pragma unroll
            for (int off = 1; off < 8; off <<= 1)
                ls += __shfl_xor_sync(0xffffffffu, ls, off);
            if (sub == 0) {
                sm.m[r] = mn;
                sm.l[r] = sm.l[r] * a + ls;
                sm.al[r] = a;
            }
        }
        __syncthreads();

        {
            const float a0 = sm.al[arow], a1 = sm.al[arow + 8];
#pragma unroll
            for (int nf = 0; nf < 8; nf++) {
                o[nf][0] *= a0; o[nf][1] *= a0;
                o[nf][2] *= a1; o[nf][3] *= a1;
            }
#pragma unroll
            for (int kb = 0; kb < 32; kb += 8) {
                const uint32_t pa0 = __float_as_uint(sm.Ss[(arow)    *SSS + kb + tig]);
                const uint32_t pa1 = __float_as_uint(sm.Ss[(arow + 8)*SSS + kb + tig]);
                const uint32_t pa2 = __float_as_uint(sm.Ss[(arow)    *SSS + kb + tig + 4]);
                const uint32_t pa3 = __float_as_uint(sm.Ss[(arow + 8)*SSS + kb + tig + 4]);
#pragma unroll
                for (int nf = 0; nf < 8; nf++) {
                    const int col = warpN * 64 + nf * 8 + gid;
                    const uint32_t b0 = __float_as_uint(sm.Vs[(kb + tig)    *VSS + col]);
                    const uint32_t b1 = __float_as_uint(sm.Vs[(kb + tig + 4)*VSS + col]);
                    mma_tf32(o[nf][0], o[nf][1], o[nf][2], o[nf][3],
                             pa0, pa1, pa2, pa3, b0, b1);
                }
            }
        }
        __syncthreads();
    }

    const float li0 = 1.0f / sm.l[arow];
    const float li1 = 1.0f / sm.l[arow + 8];
    const int row0g = q0 + arow;
#pragma unroll
    for (int nf = 0; nf < 8; nf++) {
        const int col = warpN * 64 + nf * 8 + tig * 2;
        float* p0 = g_attn + (((size_t)b * T_ + row0g)     * NH_ + h) * HD_ + col;
        float* p1 = g_attn + (((size_t)b * T_ + row0g + 8) * NH_ + h) * HD_ + col;
        *(float2*)p0 = make_float2(o[nf][0] * li0, o[nf][1] * li0);
        *(float2*)p1 = make_float2(o[nf][2] * li1, o[nf][3] * li1);
    }
}

// ---------------- launcher --------------------------------------------------------
extern "C" void kernel_launch(void* const* d_in, const int* in_sizes, int n_in,
                              void* d_out, int out_size)
{
    const float* x      = (const float*)d_in[0];
    const int*   seg    = (const int*)  d_in[1];
    const int*   cur    = (const int*)  d_in[2];
    const float* wq     = (const float*)d_in[3];
    const float* wk     = (const float*)d_in[4];
    const float* wv     = (const float*)d_in[5];
    const float* wo     = (const float*)d_in[6];
    const float* qns    = (const float*)d_in[7];
    const float* kns    = (const float*)d_in[8];
    const float* kcache = (const float*)d_in[9];
    const float* vcache = (const float*)d_in[10];
    float* out = (float*)d_out;

    float *qkvp, *wcatp, *attnp, *kcp;
    cudaGetSymbolAddress((void**)&qkvp,  g_qkv);
    cudaGetSymbolAddress((void**)&wcatp, g_wcat);
    cudaGetSymbolAddress((void**)&attnp, g_attn);
    cudaGetSymbolAddress((void**)&kcp,   g_kc);

    const int M = B_ * T_;

    // fuse weights + rope table
    wcat_kernel<<<(D_ * QKVW / 4 + 255)/256, 256>>>(wq, wk, wv);
    rope_table_kernel<<<(SC_ * 128) / 256, 256>>>();

    cudaFuncSetAttribute(gemm_tf32, cudaFuncAttributeMaxDynamicSharedMemorySize, GSMEM);

    // fused QKV projection: one launch, 1024 CTAs
    gemm_tf32<<<dim3(QKVW/128, M/128), 256, GSMEM>>>(x, wcatp, qkvp, M, QKVW, D_);

    merge_cache<<<(B_*SC_*NKV_*HD_)/256, 256>>>(kcache, vcache, cur);

    normrope_kernel<<<dim3(M, NH_),  256>>>(qkvp, qkvp, qns, seg, cur, NH_,  0,    0);
    normrope_kernel<<<dim3(M, NKV_), 256>>>(qkvp, kcp,  kns, seg, cur, NKV_, 2048, 1);

    cudaFuncSetAttribute(attn_mma, cudaFuncAttributeMaxDynamicSharedMemorySize,
                         (int)sizeof(AttnSmem));
    attn_mma<<<dim3(T_/32, NH_, B_), 256, sizeof(AttnSmem)>>>(seg);

    // output projection
    gemm_tf32<<<dim3(D_/128, M/128), 256, GSMEM>>>(attnp, wo, out, M, D_, NH_*HD_);
}

// round 9
// speedup vs baseline: 1.2909x; 1.2226x over previous
#include <cuda_runtime.h>
#include <cuda_fp16.h>
#include <math.h>
#include <stdint.h>

#define B_      2
#define T_      2048
#define D_      2048
#define NH_     8
#define NKV_    4
#define HD_     256
#define SC_     2048
#define WIN_    512
#define SOFTCAP 50.0f
#define NEGINF  -2.3819763e38f
#define QKVW    4096

// ---------------- scratch (device globals; no allocation allowed) ------------
__device__ float  g_qkv[(size_t)B_*T_*QKVW];         // fp32 q|k|v
__device__ __half g_xh[(size_t)B_*T_*D_];            // fp16 x
__device__ __half g_wqkvT[(size_t)QKVW*D_];          // fp16 [N=4096][K=2048]
__device__ __half g_woT[(size_t)D_*(NH_*HD_)];       // fp16 [N=2048][K=2048]
__device__ __half g_attn[(size_t)B_*T_*NH_*HD_];     // fp16 attention output
__device__ float  g_kc[(size_t)B_*SC_*NKV_*HD_];
__device__ float  g_vc[(size_t)B_*SC_*NKV_*HD_];
__device__ float2 g_rope[(size_t)SC_*128];

// ---------------- helpers -------------------------------------------------------
__device__ __forceinline__ uint32_t f32_to_tf32(float x) {
    uint32_t y;
    asm("cvt.rna.tf32.f32 %0, %1;" : "=r"(y) : "f"(x));
    return y;
}
__device__ __forceinline__ float round_tf32f(float x) {
    return __uint_as_float(f32_to_tf32(x));
}
__device__ __forceinline__ void tf32split(float x, float& hi, float& lo) {
    hi = round_tf32f(x);
    lo = round_tf32f(x - hi);
}

__device__ __forceinline__ void mma_tf32(float& d0, float& d1, float& d2, float& d3,
                                         uint32_t a0, uint32_t a1, uint32_t a2, uint32_t a3,
                                         uint32_t b0, uint32_t b1) {
    asm volatile("mma.sync.aligned.m16n8k8.row.col.f32.tf32.tf32.f32 "
                 "{%0,%1,%2,%3}, {%4,%5,%6,%7}, {%8,%9}, {%0,%1,%2,%3};"
                 : "+f"(d0), "+f"(d1), "+f"(d2), "+f"(d3)
                 : "r"(a0), "r"(a1), "r"(a2), "r"(a3), "r"(b0), "r"(b1));
}

__device__ __forceinline__ void mma_f16(float& d0, float& d1, float& d2, float& d3,
                                        uint32_t a0, uint32_t a1, uint32_t a2, uint32_t a3,
                                        uint32_t b0, uint32_t b1) {
    asm volatile("mma.sync.aligned.m16n8k16.row.col.f32.f16.f16.f32 "
                 "{%0,%1,%2,%3}, {%4,%5,%6,%7}, {%8,%9}, {%0,%1,%2,%3};"
                 : "+f"(d0), "+f"(d1), "+f"(d2), "+f"(d3)
                 : "r"(a0), "r"(a1), "r"(a2), "r"(a3), "r"(b0), "r"(b1));
}

__device__ __forceinline__ void cpasync16(uint32_t saddr, const void* gptr) {
    asm volatile("cp.async.cg.shared.global [%0], [%1], 16;\n" :: "r"(saddr), "l"(gptr));
}
__device__ __forceinline__ void cpasync_commit() { asm volatile("cp.async.commit_group;"); }
__device__ __forceinline__ void cpasync_wait0()  { asm volatile("cp.async.wait_group 0;"); }
__device__ __forceinline__ void cpasync_wait1()  { asm volatile("cp.async.wait_group 1;"); }

__device__ __forceinline__ float fast_tanh(float x) {
    float xc = fminf(fmaxf(x, -15.0f), 15.0f);
    float e = __expf(-2.0f * xc);
    return (1.0f - e) / (1.0f + e);
}

// ---------------- preprocessing ---------------------------------------------------
__global__ void f2h(const float* __restrict__ in, __half* __restrict__ out, int n4)
{
    const int i = blockIdx.x * 256 + threadIdx.x;
    if (i < n4) {
        float4 v = ((const float4*)in)[i];
        half2 h0 = __floats2half2_rn(v.x, v.y);
        half2 h1 = __floats2half2_rn(v.z, v.w);
        half2* dst = (half2*)(out + (size_t)i * 4);
        dst[0] = h0; dst[1] = h1;
    }
}

// w[K][N] fp32 -> wt[N][K] fp16. block (32,8), grid (N/32, K/32).
__global__ void wtrans_h(const float* __restrict__ w, __half* __restrict__ wt, int K, int N)
{
    __shared__ float tile[32][33];
    const int n0 = blockIdx.x * 32, k0 = blockIdx.y * 32;
    const int tx = threadIdx.x, ty = threadIdx.y;
#pragma unroll
    for (int i = 0; i < 32; i += 8)
        tile[ty + i][tx] = w[(size_t)(k0 + ty + i) * N + n0 + tx];
    __syncthreads();
#pragma unroll
    for (int i = 0; i < 32; i += 8)
        wt[(size_t)(n0 + ty + i) * K + k0 + tx] = __float2half_rn(tile[tx][ty + i]);
}

// ---------------- fp16 tensor-core GEMM -------------------------------------------
// C[M,N](fp32) = A[M,K](fp16) @ Bt[N,K](fp16)^T. 128x128 tile, BK=16, 3-stage.
#define AST 24                       // smem row stride in halves (48B = 12 words)
#define STG (128 * AST)              // halves per stage per operand

__global__ void __launch_bounds__(256) gemm_f16(const __half* __restrict__ A,
                                                const __half* __restrict__ Bt,
                                                float* __restrict__ C,
                                                int M, int N, int K)
{
    __shared__ __half As[3][STG];
    __shared__ __half Bs[3][STG];

    const int tid  = threadIdx.x;
    const int warp = tid >> 5;
    const int lane = tid & 31;
    const int warpM = warp >> 2;          // 0..1
    const int warpN = warp & 3;           // 0..3
    const int gid = lane >> 2;            // 0..7
    const int tig = lane & 3;             // 0..3

    const int row0 = blockIdx.y * 128;
    const int col0 = blockIdx.x * 128;

    uint32_t sA = (uint32_t)__cvta_generic_to_shared(&As[0][0]);
    uint32_t sB = (uint32_t)__cvta_generic_to_shared(&Bs[0][0]);

    const int ld_r = tid >> 1;            // 0..127
    const int ld_c = (tid & 1);           // chunk 0/1 (8 halves each)

    const int ntiles = K / 16;

    auto load_tile = [&](int kt, int st) {
        cpasync16(sA + (uint32_t)(st * STG + ld_r * AST) * 2 + ld_c * 16,
                  A + (size_t)(row0 + ld_r) * K + kt * 16 + ld_c * 8);
        cpasync16(sB + (uint32_t)(st * STG + ld_r * AST) * 2 + ld_c * 16,
                  Bt + (size_t)(col0 + ld_r) * K + kt * 16 + ld_c * 8);
    };

    float acc[4][4][4];
#pragma unroll
    for (int i = 0; i < 4; i++)
#pragma unroll
        for (int j = 0; j < 4; j++)
#pragma unroll
            for (int r = 0; r < 4; r++) acc[i][j][r] = 0.0f;

    load_tile(0, 0);
    cpasync_commit();
    load_tile(1, 1);
    cpasync_commit();

    for (int kt = 0; kt < ntiles; kt++) {
        const int st = kt % 3;
        if (kt + 1 < ntiles) cpasync_wait1(); else cpasync_wait0();
        __syncthreads();

        const __half* Ab = As[st];
        const __half* Bb = Bs[st];

        uint32_t bf[4][2];
#pragma unroll
        for (int nt = 0; nt < 4; nt++) {
            const int col = warpN * 32 + nt * 8 + gid;
            bf[nt][0] = *(const uint32_t*)&Bb[col * AST + tig * 2];
            bf[nt][1] = *(const uint32_t*)&Bb[col * AST + tig * 2 + 8];
        }
#pragma unroll
        for (int mt = 0; mt < 4; mt++) {
            const int rb = warpM * 64 + mt * 16;
            const uint32_t a0 = *(const uint32_t*)&Ab[(rb + gid)     * AST + tig * 2];
            const uint32_t a1 = *(const uint32_t*)&Ab[(rb + gid + 8) * AST + tig * 2];
            const uint32_t a2 = *(const uint32_t*)&Ab[(rb + gid)     * AST + tig * 2 + 8];
            const uint32_t a3 = *(const uint32_t*)&Ab[(rb + gid + 8) * AST + tig * 2 + 8];
#pragma unroll
            for (int nt = 0; nt < 4; nt++)
                mma_f16(acc[mt][nt][0], acc[mt][nt][1], acc[mt][nt][2], acc[mt][nt][3],
                        a0, a1, a2, a3, bf[nt][0], bf[nt][1]);
        }

        if (kt + 2 < ntiles) {
            load_tile(kt + 2, (kt + 2) % 3);
            cpasync_commit();
        }
    }

#pragma unroll
    for (int mt = 0; mt < 4; mt++) {
        const int r = row0 + warpM * 64 + mt * 16 + gid;
#pragma unroll
        for (int nt = 0; nt < 4; nt++) {
            const int c = col0 + warpN * 32 + nt * 8 + tig * 2;
            *(float2*)(C + (size_t)r * N + c)       = make_float2(acc[mt][nt][0], acc[mt][nt][1]);
            *(float2*)(C + (size_t)(r + 8) * N + c) = make_float2(acc[mt][nt][2], acc[mt][nt][3]);
        }
    }
}

// ---------------- rope table -------------------------------------------------------
__global__ void rope_table_kernel()
{
    const int idx = blockIdx.x * 256 + threadIdx.x;
    const int pos = idx >> 7;
    const int i   = idx & 127;
    const double ts  = pow(10000.0, (double)i / 128.0);
    const double ang = (double)pos / ts;
    double sn, cs;
    sincos(ang, &sn, &cs);
    g_rope[idx] = make_float2((float)cs, (float)sn);
}

// ---------------- cache merge --------------------------------------------------------
__global__ void merge_cache(const float* __restrict__ kcache,
                            const float* __restrict__ vcache,
                            const int* __restrict__ cur)
{
    const int idx = blockIdx.x * 256 + threadIdx.x;
    const int per_b = SC_ * NKV_ * HD_;
    const int b = idx / per_b;
    const int rem = idx - b * per_b;
    const int s = rem / (NKV_ * HD_);
    const int c = rem - s * (NKV_ * HD_);
    const int ci = *cur;
    const int t = s - ci;
    g_kc[idx] = kcache[idx];
    const float vv = (t >= 0 && t < T_)
        ? g_qkv[((size_t)b * T_ + t) * QKVW + 3072 + c]
        : vcache[idx];
    g_vc[idx] = round_tf32f(vv);
}

// ---------------- RMSNorm + RoPE ------------------------------------------------------
__global__ void normrope_kernel(const float* __restrict__ qkv,
                                float* __restrict__ out,
                                const float* __restrict__ scale,
                                const int* __restrict__ seg,
                                const int* __restrict__ cur,
                                int heads, int in_off, int to_cache)
{
    const int bt = blockIdx.x;
    const int h  = blockIdx.y;
    const int d  = threadIdx.x;

    const size_t in_idx = (size_t)bt * QKVW + in_off + h * HD_ + d;
    const float v = qkv[in_idx];

    float ss = v * v;
#pragma unroll
    for (int o = 16; o; o >>= 1) ss += __shfl_xor_sync(0xffffffffu, ss, o);
    __shared__ float red[8];
    __shared__ float s_ms;
    __shared__ float sh[HD_];
    const int lane = d & 31, w = d >> 5;
    if (lane == 0) red[w] = ss;
    __syncthreads();
    if (d == 0) {
        float t = 0.0f;
#pragma unroll
        for (int i = 0; i < 8; i++) t += red[i];
        s_ms = rsqrtf(t / (float)HD_ + 1e-6f);
    }
    __syncthreads();

    const float n = v * s_ms * (1.0f + scale[d]);
    sh[d] = n;
    __syncthreads();

    int pos = seg[bt];
    if (pos < 0) pos = 0;
    if (pos > SC_ - 1) pos = SC_ - 1;
    const int i = d & 127;
    const float2 cssn = g_rope[pos * 128 + i];
    const float x1 = sh[i], x2 = sh[i + 128];
    const float r = (d < 128) ? (x1 * cssn.x - x2 * cssn.y)
                              : (x2 * cssn.x + x1 * cssn.y);

    if (to_cache) {
        const int b = bt / T_, t = bt - b * T_;
        const int slot = *cur + t;
        if (slot < SC_)
            out[(((size_t)b * SC_ + slot) * heads + h) * HD_ + d] = r;
    } else {
        out[in_idx] = r;
    }
}

// ---------------- tensor-core flash attention ------------------------------------------
#define QKS 260
#define VSS 264
#define SSS 36

struct AttnSmem {
    float Qhi[32 * QKS];
    float Qlo[32 * QKS];
    float Khi[32 * QKS];
    float Klo[32 * QKS];
    float Vs [32 * VSS];
    float Ss [32 * SSS];
    float m[32], l[32], al[32];
    int   pos[32];
    int   srange[2];
};

__global__ void __launch_bounds__(256) attn_mma(const int* __restrict__ seg)
{
    extern __shared__ char smem_raw[];
    AttnSmem& sm = *reinterpret_cast<AttnSmem*>(smem_raw);

    const int tid  = threadIdx.x;
    const int warp = tid >> 5;
    const int lane = tid & 31;
    const int gid  = lane >> 2;
    const int tig  = lane & 3;
    const int warpM = warp >> 2;
    const int warpN = warp & 3;

    const int q0 = blockIdx.x * 32;
    const int h  = blockIdx.y;
    const int b  = blockIdx.z;
    const int kvh = h / (NH_ / NKV_);

    const float* qbase = g_qkv + ((size_t)b * T_ + q0) * QKVW + h * HD_;
    const float qscale = 0.0625f;
#pragma unroll
    for (int j = 0; j < 8; j++) {
        const int fi = tid + j * 256;
        const int r = fi >> 6, c4 = (fi & 63) * 4;
        float4 v = *(const float4*)(qbase + (size_t)r * QKVW + c4);
        float hv, lv;
        tf32split(v.x * qscale, hv, lv); sm.Qhi[r*QKS+c4+0]=hv; sm.Qlo[r*QKS+c4+0]=lv;
        tf32split(v.y * qscale, hv, lv); sm.Qhi[r*QKS+c4+1]=hv; sm.Qlo[r*QKS+c4+1]=lv;
        tf32split(v.z * qscale, hv, lv); sm.Qhi[r*QKS+c4+2]=hv; sm.Qlo[r*QKS+c4+2]=lv;
        tf32split(v.w * qscale, hv, lv); sm.Qhi[r*QKS+c4+3]=hv; sm.Qlo[r*QKS+c4+3]=lv;
    }
    if (tid < 32) {
        sm.m[tid] = -1e30f;
        sm.l[tid] = 0.0f;
        sm.pos[tid] = seg[b * T_ + q0 + tid];
    }
    __syncthreads();
    if (tid == 0) {
        int mn = sm.pos[0], mx = sm.pos[0];
        for (int j = 1; j < 32; j++) { mn = min(mn, sm.pos[j]); mx = max(mx, sm.pos[j]); }
        int lo = mn - (WIN_ - 1); if (lo < 0) lo = 0;
        int hi = mx; if (hi > SC_ - 1) hi = SC_ - 1;
        sm.srange[0] = lo & ~31;
        sm.srange[1] = hi;
    }
    __syncthreads();
    const int s_lo = sm.srange[0], s_hi = sm.srange[1];

    const int arow = warpM * 16 + gid;

    float o[8][4];
#pragma unroll
    for (int nf = 0; nf < 8; nf++)
#pragma unroll
        for (int r = 0; r < 4; r++) o[nf][r] = 0.0f;

    const float* kbase = g_kc + ((size_t)b * SC_ * NKV_ + kvh) * HD_;
    const float* vbase = g_vc + ((size_t)b * SC_ * NKV_ + kvh) * HD_;

    for (int s0 = s_lo; s0 <= s_hi; s0 += 32) {
#pragma unroll
        for (int j = 0; j < 8; j++) {
            const int fi = tid + j * 256;
            const int r = fi >> 6, c4 = (fi & 63) * 4;
            const int s = s0 + r;
            float4 kv = make_float4(0.f,0.f,0.f,0.f), vv = kv;
            if (s < SC_) {
                kv = *(const float4*)(kbase + (size_t)s * NKV_ * HD_ + c4);
                vv = *(const float4*)(vbase + (size_t)s * NKV_ * HD_ + c4);
            }
            float hv, lv;
            tf32split(kv.x, hv, lv); sm.Khi[r*QKS+c4+0]=hv; sm.Klo[r*QKS+c4+0]=lv;
            tf32split(kv.y, hv, lv); sm.Khi[r*QKS+c4+1]=hv; sm.Klo[r*QKS+c4+1]=lv;
            tf32split(kv.z, hv, lv); sm.Khi[r*QKS+c4+2]=hv; sm.Klo[r*QKS+c4+2]=lv;
            tf32split(kv.w, hv, lv); sm.Khi[r*QKS+c4+3]=hv; sm.Klo[r*QKS+c4+3]=lv;
            *(float4*)&sm.Vs[r*VSS+c4] = vv;
        }
        __syncthreads();

        float sc0 = 0.f, sc1 = 0.f, sc2 = 0.f, sc3 = 0.f;
        const int bcol = warpN * 8 + gid;
#pragma unroll 4
        for (int kb = 0; kb < HD_; kb += 8) {
            const uint32_t ah0 = __float_as_uint(sm.Qhi[(arow)    *QKS + kb + tig]);
            const uint32_t ah1 = __float_as_uint(sm.Qhi[(arow + 8)*QKS + kb + tig]);
            const uint32_t ah2 = __float_as_uint(sm.Qhi[(arow)    *QKS + kb + tig + 4]);
            const uint32_t ah3 = __float_as_uint(sm.Qhi[(arow + 8)*QKS + kb + tig + 4]);
            const uint32_t al0 = __float_as_uint(sm.Qlo[(arow)    *QKS + kb + tig]);
            const uint32_t al1 = __float_as_uint(sm.Qlo[(arow + 8)*QKS + kb + tig]);
            const uint32_t al2 = __float_as_uint(sm.Qlo[(arow)    *QKS + kb + tig + 4]);
            const uint32_t al3 = __float_as_uint(sm.Qlo[(arow + 8)*QKS + kb + tig + 4]);
            const uint32_t bh0 = __float_as_uint(sm.Khi[bcol*QKS + kb + tig]);
            const uint32_t bh1 = __float_as_uint(sm.Khi[bcol*QKS + kb + tig + 4]);
            const uint32_t bl0 = __float_as_uint(sm.Klo[bcol*QKS + kb + tig]);
            const uint32_t bl1 = __float_as_uint(sm.Klo[bcol*QKS + kb + tig + 4]);
            mma_tf32(sc0, sc1, sc2, sc3, ah0, ah1, ah2, ah3, bh0, bh1);
            mma_tf32(sc0, sc1, sc2, sc3, al0, al1, al2, al3, bh0, bh1);
            mma_tf32(sc0, sc1, sc2, sc3, ah0, ah1, ah2, ah3, bl0, bl1);
        }

        {
            const int c0 = warpN * 8 + tig * 2;
            const int sa = s0 + c0, sb2 = s0 + c0 + 1;
            const int qp0 = sm.pos[arow], qp1 = sm.pos[arow + 8];
            const float v0 = SOFTCAP * fast_tanh(sc0 * (1.0f / SOFTCAP));
            const float v1 = SOFTCAP * fast_tanh(sc1 * (1.0f / SOFTCAP));
            const float v2 = SOFTCAP * fast_tanh(sc2 * (1.0f / SOFTCAP));
            const float v3 = SOFTCAP * fast_tanh(sc3 * (1.0f / SOFTCAP));
            sm.Ss[(arow)    *SSS + c0    ] = (sa  <= qp0 && qp0 - sa  < WIN_ && sa  < SC_) ? v0 : NEGINF;
            sm.Ss[(arow)    *SSS + c0 + 1] = (sb2 <= qp0 && qp0 - sb2 < WIN_ && sb2 < SC_) ? v1 : NEGINF;
            sm.Ss[(arow + 8)*SSS + c0    ] = (sa  <= qp1 && qp1 - sa  < WIN_ && sa  < SC_) ? v2 : NEGINF;
            sm.Ss[(arow + 8)*SSS + c0 + 1] = (sb2 <= qp1 && qp1 - sb2 < WIN_ && sb2 < SC_) ? v3 : NEGINF;
        }
        __syncthreads();

        {
            const int r = tid >> 3, sub = tid & 7;
            float* srow = &sm.Ss[r * SSS + sub * 4];
            float mx = fmaxf(fmaxf(srow[0], srow[1]), fmaxf(srow[2], srow[3]));
#pragma unroll
            for (int off = 1; off < 8; off <<= 1)
                mx = fmaxf(mx, __shfl_xor_sync(0xffffffffu, mx, off));
            const float mo = sm.m[r];
            const float mn = fmaxf(mo, mx);
            const float a  = __expf(mo - mn);
            float ls = 0.0f;
#pragma unroll
            for (int i = 0; i < 4; i++) {
                const float p = __expf(srow[i] - mn);
                srow[i] = round_tf32f(p);
                ls += p;
            }
#pragma unroll
            for (int off = 1; off < 8; off <<= 1)
                ls += __shfl_xor_sync(0xffffffffu, ls, off);
            if (sub == 0) {
                sm.m[r] = mn;
                sm.l[r] = sm.l[r] * a + ls;
                sm.al[r] = a;
            }
        }
        __syncthreads();

        {
            const float a0 = sm.al[arow], a1 = sm.al[arow + 8];
#pragma unroll
            for (int nf = 0; nf < 8; nf++) {
                o[nf][0] *= a0; o[nf][1] *= a0;
                o[nf][2] *= a1; o[nf][3] *= a1;
            }
#pragma unroll
            for (int kb = 0; kb < 32; kb += 8) {
                const uint32_t pa0 = __float_as_uint(sm.Ss[(arow)    *SSS + kb + tig]);
                const uint32_t pa1 = __float_as_uint(sm.Ss[(arow + 8)*SSS + kb + tig]);
                const uint32_t pa2 = __float_as_uint(sm.Ss[(arow)    *SSS + kb + tig + 4]);
                const uint32_t pa3 = __float_as_uint(sm.Ss[(arow + 8)*SSS + kb + tig + 4]);
#pragma unroll
                for (int nf = 0; nf < 8; nf++) {
                    const int col = warpN * 64 + nf * 8 + gid;
                    const uint32_t b0 = __float_as_uint(sm.Vs[(kb + tig)    *VSS + col]);
                    const uint32_t b1 = __float_as_uint(sm.Vs[(kb + tig + 4)*VSS + col]);
                    mma_tf32(o[nf][0], o[nf][1], o[nf][2], o[nf][3],
                             pa0, pa1, pa2, pa3, b0, b1);
                }
            }
        }
        __syncthreads();
    }

    // epilogue: O / l, stored as fp16 (feeds o-proj A operand)
    const float li0 = 1.0f / sm.l[arow];
    const float li1 = 1.0f / sm.l[arow + 8];
    const int row0g = q0 + arow;
#pragma unroll
    for (int nf = 0; nf < 8; nf++) {
        const int col = warpN * 64 + nf * 8 + tig * 2;
        __half* p0 = g_attn + (((size_t)b * T_ + row0g)     * NH_ + h) * HD_ + col;
        __half* p1 = g_attn + (((size_t)b * T_ + row0g + 8) * NH_ + h) * HD_ + col;
        *(half2*)p0 = __floats2half2_rn(o[nf][0] * li0, o[nf][1] * li0);
        *(half2*)p1 = __floats2half2_rn(o[nf][2] * li1, o[nf][3] * li1);
    }
}

// ---------------- launcher ----------------------------------------------------------
extern "C" void kernel_launch(void* const* d_in, const int* in_sizes, int n_in,
                              void* d_out, int out_size)
{
    const float* x      = (const float*)d_in[0];
    const int*   seg    = (const int*)  d_in[1];
    const int*   cur    = (const int*)  d_in[2];
    const float* wq     = (const float*)d_in[3];
    const float* wk     = (const float*)d_in[4];
    const float* wv     = (const float*)d_in[5];
    const float* wo     = (const float*)d_in[6];
    const float* qns    = (const float*)d_in[7];
    const float* kns    = (const float*)d_in[8];
    const float* kcache = (const float*)d_in[9];
    const float* vcache = (const float*)d_in[10];
    float* out = (float*)d_out;

    float *qkvp, *kcp;
    __half *xh, *wqkvT, *woT, *attnp;
    cudaGetSymbolAddress((void**)&qkvp,  g_qkv);
    cudaGetSymbolAddress((void**)&kcp,   g_kc);
    cudaGetSymbolAddress((void**)&xh,    g_xh);
    cudaGetSymbolAddress((void**)&wqkvT, g_wqkvT);
    cudaGetSymbolAddress((void**)&woT,   g_woT);
    cudaGetSymbolAddress((void**)&attnp, g_attn);

    const int M = B_ * T_;

    // preprocessing: x -> fp16; weights -> transposed fp16
    f2h<<<((B_*T_*D_/4) + 255)/256, 256>>>(x, xh, B_*T_*D_/4);
    wtrans_h<<<dim3(2048/32, D_/32), dim3(32,8)>>>(wq, wqkvT,                       D_, 2048);
    wtrans_h<<<dim3(1024/32, D_/32), dim3(32,8)>>>(wk, wqkvT + (size_t)2048*D_,     D_, 1024);
    wtrans_h<<<dim3(1024/32, D_/32), dim3(32,8)>>>(wv, wqkvT + (size_t)3072*D_,     D_, 1024);
    wtrans_h<<<dim3(D_/32, (NH_*HD_)/32), dim3(32,8)>>>(wo, woT, NH_*HD_, D_);

    rope_table_kernel<<<(SC_ * 128) / 256, 256>>>();

    // fused QKV projection (fp16 tensor cores)
    gemm_f16<<<dim3(QKVW/128, M/128), 256>>>(xh, wqkvT, qkvp, M, QKVW, D_);

    merge_cache<<<(B_*SC_*NKV_*HD_)/256, 256>>>(kcache, vcache, cur);

    normrope_kernel<<<dim3(M, NH_),  256>>>(qkvp, qkvp, qns, seg, cur, NH_,  0,    0);
    normrope_kernel<<<dim3(M, NKV_), 256>>>(qkvp, kcp,  kns, seg, cur, NKV_, 2048, 1);

    cudaFuncSetAttribute(attn_mma, cudaFuncAttributeMaxDynamicSharedMemorySize,
                         (int)sizeof(AttnSmem));
    attn_mma<<<dim3(T_/32, NH_, B_), 256, sizeof(AttnSmem)>>>(seg);

    // output projection (fp16 tensor cores)
    gemm_f16<<<dim3(D_/128, M/128), 256>>>(attnp, woT, out, M, D_, NH_*HD_);
}

// round 10
// speedup vs baseline: 1.7904x; 1.3869x over previous
#include <cuda_runtime.h>
#include <cuda_fp16.h>
#include <math.h>
#include <stdint.h>

#define B_      2
#define T_      2048
#define D_      2048
#define NH_     8
#define NKV_    4
#define HD_     256
#define SC_     2048
#define WIN_    512
#define SOFTCAP 50.0f
#define NEGINF  -2.3819763e38f
#define QKVW    4096

// ---------------- scratch (device globals; no allocation allowed) ------------
__device__ float  g_qkv[(size_t)B_*T_*QKVW];         // fp32 q|k|v
__device__ __half g_xh[(size_t)B_*T_*D_];            // fp16 x
__device__ __half g_wqkvT[(size_t)QKVW*D_];          // fp16 [N=4096][K=2048]
__device__ __half g_woT[(size_t)D_*(NH_*HD_)];       // fp16 [N=2048][K=2048]
__device__ __half g_attn[(size_t)B_*T_*NH_*HD_];     // fp16 attention output
__device__ __half g_kch[(size_t)B_*SC_*NKV_*HD_];    // K cache hi (fp16)
__device__ __half g_kcl[(size_t)B_*SC_*NKV_*HD_];    // K cache lo (fp16)
__device__ __half g_vct[(size_t)B_*NKV_*HD_*SC_];    // V cache transposed [b][kv][d][s]
__device__ float2 g_rope[(size_t)SC_*128];

// ---------------- helpers -------------------------------------------------------
__device__ __forceinline__ void f16split(float x, __half& hi, __half& lo) {
    hi = __float2half_rn(x);
    lo = __float2half_rn(x - __half2float(hi));
}

__device__ __forceinline__ void mma_f16(float& d0, float& d1, float& d2, float& d3,
                                        uint32_t a0, uint32_t a1, uint32_t a2, uint32_t a3,
                                        uint32_t b0, uint32_t b1) {
    asm volatile("mma.sync.aligned.m16n8k16.row.col.f32.f16.f16.f32 "
                 "{%0,%1,%2,%3}, {%4,%5,%6,%7}, {%8,%9}, {%0,%1,%2,%3};"
                 : "+f"(d0), "+f"(d1), "+f"(d2), "+f"(d3)
                 : "r"(a0), "r"(a1), "r"(a2), "r"(a3), "r"(b0), "r"(b1));
}

__device__ __forceinline__ void cpasync16(uint32_t saddr, const void* gptr) {
    asm volatile("cp.async.cg.shared.global [%0], [%1], 16;\n" :: "r"(saddr), "l"(gptr));
}
__device__ __forceinline__ void cpasync_commit() { asm volatile("cp.async.commit_group;"); }
__device__ __forceinline__ void cpasync_wait0()  { asm volatile("cp.async.wait_group 0;"); }
__device__ __forceinline__ void cpasync_wait1()  { asm volatile("cp.async.wait_group 1;"); }

__device__ __forceinline__ float fast_tanh(float x) {
    float xc = fminf(fmaxf(x, -15.0f), 15.0f);
    float e = __expf(-2.0f * xc);
    return (1.0f - e) / (1.0f + e);
}

// ---------------- preprocessing ---------------------------------------------------
__global__ void f2h(const float* __restrict__ in, __half* __restrict__ out, int n4)
{
    const int i = blockIdx.x * 256 + threadIdx.x;
    if (i < n4) {
        float4 v = ((const float4*)in)[i];
        half2 h0 = __floats2half2_rn(v.x, v.y);
        half2 h1 = __floats2half2_rn(v.z, v.w);
        half2* dst = (half2*)(out + (size_t)i * 4);
        dst[0] = h0; dst[1] = h1;
    }
}

// w[K][N] fp32 -> wt[N][K] fp16
__global__ void wtrans_h(const float* __restrict__ w, __half* __restrict__ wt, int K, int N)
{
    __shared__ float tile[32][33];
    const int n0 = blockIdx.x * 32, k0 = blockIdx.y * 32;
    const int tx = threadIdx.x, ty = threadIdx.y;
#pragma unroll
    for (int i = 0; i < 32; i += 8)
        tile[ty + i][tx] = w[(size_t)(k0 + ty + i) * N + n0 + tx];
    __syncthreads();
#pragma unroll
    for (int i = 0; i < 32; i += 8)
        wt[(size_t)(n0 + ty + i) * K + k0 + tx] = __float2half_rn(tile[tx][ty + i]);
}

// ---------------- fp16 tensor-core GEMM (unchanged from R8) -----------------------
#define AST 24
#define STG (128 * AST)

__global__ void __launch_bounds__(256) gemm_f16(const __half* __restrict__ A,
                                                const __half* __restrict__ Bt,
                                                float* __restrict__ C,
                                                int M, int N, int K)
{
    __shared__ __half As[3][STG];
    __shared__ __half Bs[3][STG];

    const int tid  = threadIdx.x;
    const int warp = tid >> 5;
    const int lane = tid & 31;
    const int warpM = warp >> 2;
    const int warpN = warp & 3;
    const int gid = lane >> 2;
    const int tig = lane & 3;

    const int row0 = blockIdx.y * 128;
    const int col0 = blockIdx.x * 128;

    uint32_t sA = (uint32_t)__cvta_generic_to_shared(&As[0][0]);
    uint32_t sB = (uint32_t)__cvta_generic_to_shared(&Bs[0][0]);

    const int ld_r = tid >> 1;
    const int ld_c = (tid & 1);

    const int ntiles = K / 16;

    auto load_tile = [&](int kt, int st) {
        cpasync16(sA + (uint32_t)(st * STG + ld_r * AST) * 2 + ld_c * 16,
                  A + (size_t)(row0 + ld_r) * K + kt * 16 + ld_c * 8);
        cpasync16(sB + (uint32_t)(st * STG + ld_r * AST) * 2 + ld_c * 16,
                  Bt + (size_t)(col0 + ld_r) * K + kt * 16 + ld_c * 8);
    };

    float acc[4][4][4];
#pragma unroll
    for (int i = 0; i < 4; i++)
#pragma unroll
        for (int j = 0; j < 4; j++)
#pragma unroll
            for (int r = 0; r < 4; r++) acc[i][j][r] = 0.0f;

    load_tile(0, 0);
    cpasync_commit();
    load_tile(1, 1);
    cpasync_commit();

    for (int kt = 0; kt < ntiles; kt++) {
        const int st = kt % 3;
        if (kt + 1 < ntiles) cpasync_wait1(); else cpasync_wait0();
        __syncthreads();

        const __half* Ab = As[st];
        const __half* Bb = Bs[st];

        uint32_t bf[4][2];
#pragma unroll
        for (int nt = 0; nt < 4; nt++) {
            const int col = warpN * 32 + nt * 8 + gid;
            bf[nt][0] = *(const uint32_t*)&Bb[col * AST + tig * 2];
            bf[nt][1] = *(const uint32_t*)&Bb[col * AST + tig * 2 + 8];
        }
#pragma unroll
        for (int mt = 0; mt < 4; mt++) {
            const int rb = warpM * 64 + mt * 16;
            const uint32_t a0 = *(const uint32_t*)&Ab[(rb + gid)     * AST + tig * 2];
            const uint32_t a1 = *(const uint32_t*)&Ab[(rb + gid + 8) * AST + tig * 2];
            const uint32_t a2 = *(const uint32_t*)&Ab[(rb + gid)     * AST + tig * 2 + 8];
            const uint32_t a3 = *(const uint32_t*)&Ab[(rb + gid + 8) * AST + tig * 2 + 8];
#pragma unroll
            for (int nt = 0; nt < 4; nt++)
                mma_f16(acc[mt][nt][0], acc[mt][nt][1], acc[mt][nt][2], acc[mt][nt][3],
                        a0, a1, a2, a3, bf[nt][0], bf[nt][1]);
        }

        if (kt + 2 < ntiles) {
            load_tile(kt + 2, (kt + 2) % 3);
            cpasync_commit();
        }
    }

#pragma unroll
    for (int mt = 0; mt < 4; mt++) {
        const int r = row0 + warpM * 64 + mt * 16 + gid;
#pragma unroll
        for (int nt = 0; nt < 4; nt++) {
            const int c = col0 + warpN * 32 + nt * 8 + tig * 2;
            *(float2*)(C + (size_t)r * N + c)       = make_float2(acc[mt][nt][0], acc[mt][nt][1]);
            *(float2*)(C + (size_t)(r + 8) * N + c) = make_float2(acc[mt][nt][2], acc[mt][nt][3]);
        }
    }
}

// ---------------- rope table -------------------------------------------------------
__global__ void rope_table_kernel()
{
    const int idx = blockIdx.x * 256 + threadIdx.x;
    const int pos = idx >> 7;
    const int i   = idx & 127;
    const double ts  = pow(10000.0, (double)i / 128.0);
    const double ang = (double)pos / ts;
    double sn, cs;
    sincos(ang, &sn, &cs);
    g_rope[idx] = make_float2((float)cs, (float)sn);
}

// ---------------- K cache merge (split to fp16 hi/lo) -------------------------------
__global__ void merge_k(const float* __restrict__ kcache)
{
    const int idx = blockIdx.x * 256 + threadIdx.x;   // < B*SC*NKV*HD
    const float v = kcache[idx];
    __half hi, lo;
    f16split(v, hi, lo);
    g_kch[idx] = hi;
    g_kcl[idx] = lo;
}

// ---------------- V cache: select + transpose + fp16 --------------------------------
// grid (SC/32, HD/32, B*NKV), block (32, 8)
__global__ void vtrans_cache(const float* __restrict__ vcache, const int* __restrict__ cur)
{
    __shared__ float tile[32][33];
    const int s0 = blockIdx.x * 32, d0 = blockIdx.y * 32;
    const int bk = blockIdx.z;
    const int b = bk / NKV_, kv = bk % NKV_;
    const int tx = threadIdx.x, ty = threadIdx.y;
    const int ci = *cur;
#pragma unroll
    for (int i = 0; i < 32; i += 8) {
        const int s = s0 + ty + i;
        const int t = s - ci;
        const float v = (t >= 0 && t < T_)
            ? g_qkv[((size_t)b * T_ + t) * QKVW + 3072 + kv * HD_ + d0 + tx]
            : vcache[(((size_t)b * SC_ + s) * NKV_ + kv) * HD_ + d0 + tx];
        tile[ty + i][tx] = v;
    }
    __syncthreads();
#pragma unroll
    for (int i = 0; i < 32; i += 8) {
        const int d = d0 + ty + i;
        g_vct[((size_t)(b * NKV_ + kv) * HD_ + d) * SC_ + s0 + tx] =
            __float2half_rn(tile[tx][ty + i]);
    }
}

// ---------------- RMSNorm + RoPE -----------------------------------------------------
// to_cache=0: in-place fp32 on q region of g_qkv. to_cache=1: write split fp16 K cache.
__global__ void normrope_kernel(const float* __restrict__ qkv,
                                const float* __restrict__ scale,
                                const int* __restrict__ seg,
                                const int* __restrict__ cur,
                                int heads, int in_off, int to_cache)
{
    const int bt = blockIdx.x;
    const int h  = blockIdx.y;
    const int d  = threadIdx.x;

    const size_t in_idx = (size_t)bt * QKVW + in_off + h * HD_ + d;
    const float v = qkv[in_idx];

    float ss = v * v;
#pragma unroll
    for (int o = 16; o; o >>= 1) ss += __shfl_xor_sync(0xffffffffu, ss, o);
    __shared__ float red[8];
    __shared__ float s_ms;
    __shared__ float sh[HD_];
    const int lane = d & 31, w = d >> 5;
    if (lane == 0) red[w] = ss;
    __syncthreads();
    if (d == 0) {
        float t = 0.0f;
#pragma unroll
        for (int i = 0; i < 8; i++) t += red[i];
        s_ms = rsqrtf(t / (float)HD_ + 1e-6f);
    }
    __syncthreads();

    const float n = v * s_ms * (1.0f + scale[d]);
    sh[d] = n;
    __syncthreads();

    int pos = seg[bt];
    if (pos < 0) pos = 0;
    if (pos > SC_ - 1) pos = SC_ - 1;
    const int i = d & 127;
    const float2 cssn = g_rope[pos * 128 + i];
    const float x1 = sh[i], x2 = sh[i + 128];
    const float r = (d < 128) ? (x1 * cssn.x - x2 * cssn.y)
                              : (x2 * cssn.x + x1 * cssn.y);

    if (to_cache) {
        const int b = bt / T_, t = bt - b * T_;
        const int slot = *cur + t;
        if (slot < SC_) {
            const size_t oi = (((size_t)b * SC_ + slot) * heads + h) * HD_ + d;
            __half hi, lo;
            f16split(r, hi, lo);
            g_kch[oi] = hi;
            g_kcl[oi] = lo;
        }
    } else {
        ((float*)qkv)[in_idx] = r;
    }
}

// ---------------- fp16 tensor-core flash attention ------------------------------------
#define QKH 264    // Q/K smem row stride (halves): 132 words -> 4*gid+tig bank map
#define VTS 40     // Vt / Ph row stride (halves): 20 words -> 20*gid+tig bank map
#define SSS 36     // Ss fp32 row stride

struct AttnSmemH {
    __half Qhi[32 * QKH];
    __half Qlo[32 * QKH];
    __half Khi[32 * QKH];
    __half Klo[32 * QKH];
    __half Vt [256 * VTS];   // [dim][key]
    __half Ph [32 * VTS];    // probabilities fp16
    float  Ss [32 * SSS];    // masked logits fp32
    float m[32], l[32], al[32];
    int   pos[32];
    int   srange[2];
};

__global__ void __launch_bounds__(256, 2) attn_f16(const int* __restrict__ seg)
{
    extern __shared__ char smem_raw[];
    AttnSmemH& sm = *reinterpret_cast<AttnSmemH*>(smem_raw);

    const int tid  = threadIdx.x;
    const int warp = tid >> 5;
    const int lane = tid & 31;
    const int gid  = lane >> 2;
    const int tig  = lane & 3;
    const int warpM = warp >> 2;
    const int warpN = warp & 3;

    const int q0 = blockIdx.x * 32;
    const int h  = blockIdx.y;
    const int b  = blockIdx.z;
    const int kvh = h / (NH_ / NKV_);

    // ---- Q load: scale + fp16 split ----
    const float* qbase = g_qkv + ((size_t)b * T_ + q0) * QKVW + h * HD_;
    const float qscale = 0.0625f;
#pragma unroll
    for (int j = 0; j < 8; j++) {
        const int fi = tid + j * 256;
        const int r = fi >> 6, c4 = (fi & 63) * 4;
        float4 v = *(const float4*)(qbase + (size_t)r * QKVW + c4);
        __half h0, l0, h1, l1, h2, l2, h3, l3;
        f16split(v.x * qscale, h0, l0);
        f16split(v.y * qscale, h1, l1);
        f16split(v.z * qscale, h2, l2);
        f16split(v.w * qscale, h3, l3);
        *(half2*)&sm.Qhi[r*QKH + c4]     = __halves2half2(h0, h1);
        *(half2*)&sm.Qhi[r*QKH + c4 + 2] = __halves2half2(h2, h3);
        *(half2*)&sm.Qlo[r*QKH + c4]     = __halves2half2(l0, l1);
        *(half2*)&sm.Qlo[r*QKH + c4 + 2] = __halves2half2(l2, l3);
    }
    if (tid < 32) {
        sm.m[tid] = -1e30f;
        sm.l[tid] = 0.0f;
        sm.pos[tid] = seg[b * T_ + q0 + tid];
    }
    __syncthreads();
    if (tid == 0) {
        int mn = sm.pos[0], mx = sm.pos[0];
        for (int j = 1; j < 32; j++) { mn = min(mn, sm.pos[j]); mx = max(mx, sm.pos[j]); }
        int lo = mn - (WIN_ - 1); if (lo < 0) lo = 0;
        int hi = mx; if (hi > SC_ - 1) hi = SC_ - 1;
        sm.srange[0] = lo & ~31;
        sm.srange[1] = hi;
    }
    __syncthreads();
    const int s_lo = sm.srange[0], s_hi = sm.srange[1];

    const int arow = warpM * 16 + gid;

    float o[8][4];
#pragma unroll
    for (int nf = 0; nf < 8; nf++)
#pragma unroll
        for (int r = 0; r < 4; r++) o[nf][r] = 0.0f;

    const __half* khbase = g_kch + ((size_t)b * SC_ * NKV_ + kvh) * HD_;
    const __half* klbase = g_kcl + ((size_t)b * SC_ * NKV_ + kvh) * HD_;
    const __half* vtbase = g_vct + (size_t)(b * NKV_ + kvh) * HD_ * SC_;

    for (int s0 = s_lo; s0 <= s_hi; s0 += 32) {
        // ---- K tile (hi/lo) + V tile (transposed) ----
#pragma unroll
        for (int j = 0; j < 4; j++) {
            const int fi = tid + j * 256;
            const int r = fi >> 5, c8 = (fi & 31) * 8;     // 32 keys x 256 dims
            *(uint4*)&sm.Khi[r*QKH + c8] =
                *(const uint4*)(khbase + (size_t)(s0 + r) * NKV_ * HD_ + c8);
            *(uint4*)&sm.Klo[r*QKH + c8] =
                *(const uint4*)(klbase + (size_t)(s0 + r) * NKV_ * HD_ + c8);
        }
#pragma unroll
        for (int j = 0; j < 4; j++) {
            const int fi = tid + j * 256;
            const int d = fi >> 2, c8 = (fi & 3) * 8;      // 256 dims x 32 keys
            *(uint4*)&sm.Vt[d*VTS + c8] =
                *(const uint4*)(vtbase + (size_t)d * SC_ + s0 + c8);
        }
        __syncthreads();

        // ---- QK^T: split fp16, 3 mma per k16 ----
        float sc0 = 0.f, sc1 = 0.f, sc2 = 0.f, sc3 = 0.f;
        const int bcol = warpN * 8 + gid;
#pragma unroll
        for (int kb = 0; kb < HD_; kb += 16) {
            const uint32_t qh0 = *(const uint32_t*)&sm.Qhi[(arow)    *QKH + kb + tig*2];
            const uint32_t qh1 = *(const uint32_t*)&sm.Qhi[(arow + 8)*QKH + kb + tig*2];
            const uint32_t qh2 = *(const uint32_t*)&sm.Qhi[(arow)    *QKH + kb + 8 + tig*2];
            const uint32_t qh3 = *(const uint32_t*)&sm.Qhi[(arow + 8)*QKH + kb + 8 + tig*2];
            const uint32_t ql0 = *(const uint32_t*)&sm.Qlo[(arow)    *QKH + kb + tig*2];
            const uint32_t ql1 = *(const uint32_t*)&sm.Qlo[(arow + 8)*QKH + kb + tig*2];
            const uint32_t ql2 = *(const uint32_t*)&sm.Qlo[(arow)    *QKH + kb + 8 + tig*2];
            const uint32_t ql3 = *(const uint32_t*)&sm.Qlo[(arow + 8)*QKH + kb + 8 + tig*2];
            const uint32_t kh0 = *(const uint32_t*)&sm.Khi[bcol*QKH + kb + tig*2];
            const uint32_t kh1 = *(const uint32_t*)&sm.Khi[bcol*QKH + kb + 8 + tig*2];
            const uint32_t kl0 = *(const uint32_t*)&sm.Klo[bcol*QKH + kb + tig*2];
            const uint32_t kl1 = *(const uint32_t*)&sm.Klo[bcol*QKH + kb + 8 + tig*2];
            mma_f16(sc0, sc1, sc2, sc3, qh0, qh1, qh2, qh3, kh0, kh1);
            mma_f16(sc0, sc1, sc2, sc3, ql0, ql1, ql2, ql3, kh0, kh1);
            mma_f16(sc0, sc1, sc2, sc3, qh0, qh1, qh2, qh3, kl0, kl1);
        }

        // ---- softcap + mask ----
        {
            const int c0 = warpN * 8 + tig * 2;
            const int sa = s0 + c0, sb2 = s0 + c0 + 1;
            const int qp0 = sm.pos[arow], qp1 = sm.pos[arow + 8];
            const float v0 = SOFTCAP * fast_tanh(sc0 * (1.0f / SOFTCAP));
            const float v1 = SOFTCAP * fast_tanh(sc1 * (1.0f / SOFTCAP));
            const float v2 = SOFTCAP * fast_tanh(sc2 * (1.0f / SOFTCAP));
            const float v3 = SOFTCAP * fast_tanh(sc3 * (1.0f / SOFTCAP));
            sm.Ss[(arow)    *SSS + c0    ] = (sa  <= qp0 && qp0 - sa  < WIN_) ? v0 : NEGINF;
            sm.Ss[(arow)    *SSS + c0 + 1] = (sb2 <= qp0 && qp0 - sb2 < WIN_) ? v1 : NEGINF;
            sm.Ss[(arow + 8)*SSS + c0    ] = (sa  <= qp1 && qp1 - sa  < WIN_) ? v2 : NEGINF;
            sm.Ss[(arow + 8)*SSS + c0 + 1] = (sb2 <= qp1 && qp1 - sb2 < WIN_) ? v3 : NEGINF;
        }
        __syncthreads();

        // ---- online softmax; write P as fp16 ----
        {
            const int r = tid >> 3, sub = tid & 7;
            const float* srow = &sm.Ss[r * SSS + sub * 4];
            float mx = fmaxf(fmaxf(srow[0], srow[1]), fmaxf(srow[2], srow[3]));
#pragma unroll
            for (int off = 1; off < 8; off <<= 1)
                mx = fmaxf(mx, __shfl_xor_sync(0xffffffffu, mx, off));
            const float mo = sm.m[r];
            const float mn = fmaxf(mo, mx);
            const float a  = __expf(mo - mn);
            const float p0 = __expf(srow[0] - mn);
            const float p1 = __expf(srow[1] - mn);
            const float p2 = __expf(srow[2] - mn);
            const float p3 = __expf(srow[3] - mn);
            float ls = p0 + p1 + p2 + p3;
            *(half2*)&sm.Ph[r * VTS + sub * 4]     = __floats2half2_rn(p0, p1);
            *(half2*)&sm.Ph[r * VTS + sub * 4 + 2] = __floats2half2_rn(p2, p3);
#pragma unroll
            for (int off = 1; off < 8; off <<= 1)
                ls += __shfl_xor_sync(0xffffffffu, ls, off);
            if (sub == 0) {
                sm.m[r] = mn;
                sm.l[r] = sm.l[r] * a + ls;
                sm.al[r] = a;
            }
        }
        __syncthreads();

        // ---- P @ V (fp16) ----
        {
            const float a0 = sm.al[arow], a1 = sm.al[arow + 8];
#pragma unroll
            for (int nf = 0; nf < 8; nf++) {
                o[nf][0] *= a0; o[nf][1] *= a0;
                o[nf][2] *= a1; o[nf][3] *= a1;
            }
#pragma unroll
            for (int kb = 0; kb < 32; kb += 16) {
                const uint32_t pa0 = *(const uint32_t*)&sm.Ph[(arow)    *VTS + kb + tig*2];
                const uint32_t pa1 = *(const uint32_t*)&sm.Ph[(arow + 8)*VTS + kb + tig*2];
                const uint32_t pa2 = *(const uint32_t*)&sm.Ph[(arow)    *VTS + kb + 8 + tig*2];
                const uint32_t pa3 = *(const uint32_t*)&sm.Ph[(arow + 8)*VTS + kb + 8 + tig*2];
#pragma unroll
                for (int nf = 0; nf < 8; nf++) {
                    const int col = warpN * 64 + nf * 8 + gid;
                    const uint32_t b0 = *(const uint32_t*)&sm.Vt[col*VTS + kb + tig*2];
                    const uint32_t b1 = *(const uint32_t*)&sm.Vt[col*VTS + kb + 8 + tig*2];
                    mma_f16(o[nf][0], o[nf][1], o[nf][2], o[nf][3],
                            pa0, pa1, pa2, pa3, b0, b1);
                }
            }
        }
        __syncthreads();
    }

    // ---- epilogue: O / l, fp16 out ----
    const float li0 = 1.0f / sm.l[arow];
    const float li1 = 1.0f / sm.l[arow + 8];
    const int row0g = q0 + arow;
#pragma unroll
    for (int nf = 0; nf < 8; nf++) {
        const int col = warpN * 64 + nf * 8 + tig * 2;
        __half* p0 = g_attn + (((size_t)b * T_ + row0g)     * NH_ + h) * HD_ + col;
        __half* p1 = g_attn + (((size_t)b * T_ + row0g + 8) * NH_ + h) * HD_ + col;
        *(half2*)p0 = __floats2half2_rn(o[nf][0] * li0, o[nf][1] * li0);
        *(half2*)p1 = __floats2half2_rn(o[nf][2] * li1, o[nf][3] * li1);
    }
}

// ---------------- launcher ----------------------------------------------------------
extern "C" void kernel_launch(void* const* d_in, const int* in_sizes, int n_in,
                              void* d_out, int out_size)
{
    const float* x      = (const float*)d_in[0];
    const int*   seg    = (const int*)  d_in[1];
    const int*   cur    = (const int*)  d_in[2];
    const float* wq     = (const float*)d_in[3];
    const float* wk     = (const float*)d_in[4];
    const float* wv     = (const float*)d_in[5];
    const float* wo     = (const float*)d_in[6];
    const float* qns    = (const float*)d_in[7];
    const float* kns    = (const float*)d_in[8];
    const float* kcache = (const float*)d_in[9];
    const float* vcache = (const float*)d_in[10];
    float* out = (float*)d_out;

    float *qkvp;
    __half *xh, *wqkvT, *woT, *attnp;
    cudaGetSymbolAddress((void**)&qkvp,  g_qkv);
    cudaGetSymbolAddress((void**)&xh,    g_xh);
    cudaGetSymbolAddress((void**)&wqkvT, g_wqkvT);
    cudaGetSymbolAddress((void**)&woT,   g_woT);
    cudaGetSymbolAddress((void**)&attnp, g_attn);

    const int M = B_ * T_;

    // preprocessing
    f2h<<<((B_*T_*D_/4) + 255)/256, 256>>>(x, xh, B_*T_*D_/4);
    wtrans_h<<<dim3(2048/32, D_/32), dim3(32,8)>>>(wq, wqkvT,                   D_, 2048);
    wtrans_h<<<dim3(1024/32, D_/32), dim3(32,8)>>>(wk, wqkvT + (size_t)2048*D_, D_, 1024);
    wtrans_h<<<dim3(1024/32, D_/32), dim3(32,8)>>>(wv, wqkvT + (size_t)3072*D_, D_, 1024);
    wtrans_h<<<dim3(D_/32, (NH_*HD_)/32), dim3(32,8)>>>(wo, woT, NH_*HD_, D_);

    rope_table_kernel<<<(SC_ * 128) / 256, 256>>>();

    // fused QKV projection
    gemm_f16<<<dim3(QKVW/128, M/128), 256>>>(xh, wqkvT, qkvp, M, QKVW, D_);

    // caches
    merge_k<<<(B_*SC_*NKV_*HD_)/256, 256>>>(kcache);
    vtrans_cache<<<dim3(SC_/32, HD_/32, B_*NKV_), dim3(32,8)>>>(vcache, cur);

    normrope_kernel<<<dim3(M, NH_),  256>>>(qkvp, qns, seg, cur, NH_,  0,    0);
    normrope_kernel<<<dim3(M, NKV_), 256>>>(qkvp, kns, seg, cur, NKV_, 2048, 1);

    cudaFuncSetAttribute(attn_f16, cudaFuncAttributeMaxDynamicSharedMemorySize,
                         (int)sizeof(AttnSmemH));
    attn_f16<<<dim3(T_/32, NH_, B_), 256, sizeof(AttnSmemH)>>>(seg);

    // output projection
    gemm_f16<<<dim3(D_/128, M/128), 256>>>(attnp, woT, out, M, D_, NH_*HD_);
}

// round 11
// speedup vs baseline: 1.9731x; 1.1021x over previous
#include <cuda_runtime.h>
#include <cuda_fp16.h>
#include <math.h>
#include <stdint.h>

#define B_      2
#define T_      2048
#define D_      2048
#define NH_     8
#define NKV_    4
#define HD_     256
#define SC_     2048
#define WIN_    512
#define SOFTCAP 50.0f
#define NEGINF  -2.3819763e38f
#define QKVW    4096

// ---------------- scratch (device globals; no allocation allowed) ------------
__device__ float  g_qkv[(size_t)B_*T_*QKVW];         // fp32 q|k|v
__device__ __half g_xh[(size_t)B_*T_*D_];            // fp16 x
__device__ __half g_wqkvT[(size_t)QKVW*D_];          // fp16 [N=4096][K=2048]
__device__ __half g_woT[(size_t)D_*(NH_*HD_)];       // fp16 [N=2048][K=2048]
__device__ __half g_attn[(size_t)B_*T_*NH_*HD_];     // fp16 attention output
__device__ __half g_kch[(size_t)B_*SC_*NKV_*HD_];    // K cache (fp16)
__device__ __half g_vct[(size_t)B_*NKV_*HD_*SC_];    // V cache transposed [b][kv][d][s]
__device__ float2 g_rope[(size_t)SC_*128];

// ---------------- helpers -------------------------------------------------------
__device__ __forceinline__ void f16split(float x, __half& hi, __half& lo) {
    hi = __float2half_rn(x);
    lo = __float2half_rn(x - __half2float(hi));
}

__device__ __forceinline__ void mma_f16(float& d0, float& d1, float& d2, float& d3,
                                        uint32_t a0, uint32_t a1, uint32_t a2, uint32_t a3,
                                        uint32_t b0, uint32_t b1) {
    asm volatile("mma.sync.aligned.m16n8k16.row.col.f32.f16.f16.f32 "
                 "{%0,%1,%2,%3}, {%4,%5,%6,%7}, {%8,%9}, {%0,%1,%2,%3};"
                 : "+f"(d0), "+f"(d1), "+f"(d2), "+f"(d3)
                 : "r"(a0), "r"(a1), "r"(a2), "r"(a3), "r"(b0), "r"(b1));
}

__device__ __forceinline__ void cpasync16(uint32_t saddr, const void* gptr) {
    asm volatile("cp.async.cg.shared.global [%0], [%1], 16;\n" :: "r"(saddr), "l"(gptr));
}
__device__ __forceinline__ void cpasync_commit() { asm volatile("cp.async.commit_group;"); }
__device__ __forceinline__ void cpasync_wait0()  { asm volatile("cp.async.wait_group 0;"); }
__device__ __forceinline__ void cpasync_wait1()  { asm volatile("cp.async.wait_group 1;"); }

__device__ __forceinline__ float fast_tanh(float x) {
    float xc = fminf(fmaxf(x, -15.0f), 15.0f);
    float e = __expf(-2.0f * xc);
    return (1.0f - e) / (1.0f + e);
}

// ---------------- preprocessing ---------------------------------------------------
__global__ void f2h(const float* __restrict__ in, __half* __restrict__ out, int n4)
{
    const int i = blockIdx.x * 256 + threadIdx.x;
    if (i < n4) {
        float4 v = ((const float4*)in)[i];
        half2 h0 = __floats2half2_rn(v.x, v.y);
        half2 h1 = __floats2half2_rn(v.z, v.w);
        half2* dst = (half2*)(out + (size_t)i * 4);
        dst[0] = h0; dst[1] = h1;
    }
}

// w[K][N] fp32 -> wt[N][K] fp16
__global__ void wtrans_h(const float* __restrict__ w, __half* __restrict__ wt, int K, int N)
{
    __shared__ float tile[32][33];
    const int n0 = blockIdx.x * 32, k0 = blockIdx.y * 32;
    const int tx = threadIdx.x, ty = threadIdx.y;
#pragma unroll
    for (int i = 0; i < 32; i += 8)
        tile[ty + i][tx] = w[(size_t)(k0 + ty + i) * N + n0 + tx];
    __syncthreads();
#pragma unroll
    for (int i = 0; i < 32; i += 8)
        wt[(size_t)(n0 + ty + i) * K + k0 + tx] = __float2half_rn(tile[tx][ty + i]);
}

// ---------------- fp16 tensor-core GEMM: BK=32, 3-stage, 64 barriers ---------------
#define AST2 40                       // smem row stride (halves): 20 words, conflict-free
#define STG2 (128 * AST2)
#define GSMEM (3 * 2 * STG2 * 2)      // 3 stages x 2 operands x halves x 2B = 61440

__global__ void __launch_bounds__(256) gemm_f16(const __half* __restrict__ A,
                                                const __half* __restrict__ Bt,
                                                float* __restrict__ C,
                                                int M, int N, int K)
{
    extern __shared__ __half hs[];
    __half* As = hs;                  // [3][STG2]
    __half* Bs = hs + 3 * STG2;       // [3][STG2]

    const int tid  = threadIdx.x;
    const int warp = tid >> 5;
    const int lane = tid & 31;
    const int warpM = warp >> 2;
    const int warpN = warp & 3;
    const int gid = lane >> 2;
    const int tig = lane & 3;

    const int row0 = blockIdx.y * 128;
    const int col0 = blockIdx.x * 128;

    uint32_t sA = (uint32_t)__cvta_generic_to_shared(As);
    uint32_t sB = (uint32_t)__cvta_generic_to_shared(Bs);

    const int ld_r = tid >> 1;           // 0..127
    const int ld_c = (tid & 1) * 2;      // chunk base 0 or 2 (of 4 x 16B per row)

    const int ntiles = K / 32;

    auto load_tile = [&](int kt, int st) {
#pragma unroll
        for (int c = 0; c < 2; c++) {
            cpasync16(sA + (uint32_t)(st * STG2 + ld_r * AST2) * 2 + (ld_c + c) * 16,
                      A + (size_t)(row0 + ld_r) * K + kt * 32 + (ld_c + c) * 8);
            cpasync16(sB + (uint32_t)(st * STG2 + ld_r * AST2) * 2 + (ld_c + c) * 16,
                      Bt + (size_t)(col0 + ld_r) * K + kt * 32 + (ld_c + c) * 8);
        }
    };

    float acc[4][4][4];
#pragma unroll
    for (int i = 0; i < 4; i++)
#pragma unroll
        for (int j = 0; j < 4; j++)
#pragma unroll
            for (int r = 0; r < 4; r++) acc[i][j][r] = 0.0f;

    load_tile(0, 0);
    cpasync_commit();
    load_tile(1, 1);
    cpasync_commit();

    for (int kt = 0; kt < ntiles; kt++) {
        const int st = kt % 3;
        if (kt + 1 < ntiles) cpasync_wait1(); else cpasync_wait0();
        __syncthreads();

        const __half* Ab = As + st * STG2;
        const __half* Bb = Bs + st * STG2;

#pragma unroll
        for (int ks = 0; ks < 2; ks++) {
            const int kb = ks * 16;
            uint32_t bf[4][2];
#pragma unroll
            for (int nt = 0; nt < 4; nt++) {
                const int col = warpN * 32 + nt * 8 + gid;
                bf[nt][0] = *(const uint32_t*)&Bb[col * AST2 + kb + tig * 2];
                bf[nt][1] = *(const uint32_t*)&Bb[col * AST2 + kb + tig * 2 + 8];
            }
#pragma unroll
            for (int mt = 0; mt < 4; mt++) {
                const int rb = warpM * 64 + mt * 16;
                const uint32_t a0 = *(const uint32_t*)&Ab[(rb + gid)     * AST2 + kb + tig * 2];
                const uint32_t a1 = *(const uint32_t*)&Ab[(rb + gid + 8) * AST2 + kb + tig * 2];
                const uint32_t a2 = *(const uint32_t*)&Ab[(rb + gid)     * AST2 + kb + tig * 2 + 8];
                const uint32_t a3 = *(const uint32_t*)&Ab[(rb + gid + 8) * AST2 + kb + tig * 2 + 8];
#pragma unroll
                for (int nt = 0; nt < 4; nt++)
                    mma_f16(acc[mt][nt][0], acc[mt][nt][1], acc[mt][nt][2], acc[mt][nt][3],
                            a0, a1, a2, a3, bf[nt][0], bf[nt][1]);
            }
        }

        if (kt + 2 < ntiles) {
            load_tile(kt + 2, (kt + 2) % 3);
            cpasync_commit();
        }
    }

#pragma unroll
    for (int mt = 0; mt < 4; mt++) {
        const int r = row0 + warpM * 64 + mt * 16 + gid;
#pragma unroll
        for (int nt = 0; nt < 4; nt++) {
            const int c = col0 + warpN * 32 + nt * 8 + tig * 2;
            *(float2*)(C + (size_t)r * N + c)       = make_float2(acc[mt][nt][0], acc[mt][nt][1]);
            *(float2*)(C + (size_t)(r + 8) * N + c) = make_float2(acc[mt][nt][2], acc[mt][nt][3]);
        }
    }
}

// ---------------- rope table -------------------------------------------------------
__global__ void rope_table_kernel()
{
    const int idx = blockIdx.x * 256 + threadIdx.x;
    const int pos = idx >> 7;
    const int i   = idx & 127;
    const double ts  = pow(10000.0, (double)i / 128.0);
    const double ang = (double)pos / ts;
    double sn, cs;
    sincos(ang, &sn, &cs);
    g_rope[idx] = make_float2((float)cs, (float)sn);
}

// ---------------- K cache merge (fp16) -----------------------------------------------
__global__ void merge_k(const float* __restrict__ kcache)
{
    const int i = blockIdx.x * 256 + threadIdx.x;      // float4 index
    float4 v = ((const float4*)kcache)[i];
    half2* dst = (half2*)(g_kch + (size_t)i * 4);
    dst[0] = __floats2half2_rn(v.x, v.y);
    dst[1] = __floats2half2_rn(v.z, v.w);
}

// ---------------- V cache: select + transpose + fp16 ----------------------------------
__global__ void vtrans_cache(const float* __restrict__ vcache, const int* __restrict__ cur)
{
    __shared__ float tile[32][33];
    const int s0 = blockIdx.x * 32, d0 = blockIdx.y * 32;
    const int bk = blockIdx.z;
    const int b = bk / NKV_, kv = bk % NKV_;
    const int tx = threadIdx.x, ty = threadIdx.y;
    const int ci = *cur;
#pragma unroll
    for (int i = 0; i < 32; i += 8) {
        const int s = s0 + ty + i;
        const int t = s - ci;
        const float v = (t >= 0 && t < T_)
            ? g_qkv[((size_t)b * T_ + t) * QKVW + 3072 + kv * HD_ + d0 + tx]
            : vcache[(((size_t)b * SC_ + s) * NKV_ + kv) * HD_ + d0 + tx];
        tile[ty + i][tx] = v;
    }
    __syncthreads();
#pragma unroll
    for (int i = 0; i < 32; i += 8) {
        const int d = d0 + ty + i;
        g_vct[((size_t)(b * NKV_ + kv) * HD_ + d) * SC_ + s0 + tx] =
            __float2half_rn(tile[tx][ty + i]);
    }
}

// ---------------- RMSNorm + RoPE ------------------------------------------------------
__global__ void normrope_kernel(const float* __restrict__ qkv,
                                const float* __restrict__ scale,
                                const int* __restrict__ seg,
                                const int* __restrict__ cur,
                                int heads, int in_off, int to_cache)
{
    const int bt = blockIdx.x;
    const int h  = blockIdx.y;
    const int d  = threadIdx.x;

    const size_t in_idx = (size_t)bt * QKVW + in_off + h * HD_ + d;
    const float v = qkv[in_idx];

    float ss = v * v;
#pragma unroll
    for (int o = 16; o; o >>= 1) ss += __shfl_xor_sync(0xffffffffu, ss, o);
    __shared__ float red[8];
    __shared__ float s_ms;
    __shared__ float sh[HD_];
    const int lane = d & 31, w = d >> 5;
    if (lane == 0) red[w] = ss;
    __syncthreads();
    if (d == 0) {
        float t = 0.0f;
#pragma unroll
        for (int i = 0; i < 8; i++) t += red[i];
        s_ms = rsqrtf(t / (float)HD_ + 1e-6f);
    }
    __syncthreads();

    const float n = v * s_ms * (1.0f + scale[d]);
    sh[d] = n;
    __syncthreads();

    int pos = seg[bt];
    if (pos < 0) pos = 0;
    if (pos > SC_ - 1) pos = SC_ - 1;
    const int i = d & 127;
    const float2 cssn = g_rope[pos * 128 + i];
    const float x1 = sh[i], x2 = sh[i + 128];
    const float r = (d < 128) ? (x1 * cssn.x - x2 * cssn.y)
                              : (x2 * cssn.x + x1 * cssn.y);

    if (to_cache) {
        const int b = bt / T_, t = bt - b * T_;
        const int slot = *cur + t;
        if (slot < SC_)
            g_kch[(((size_t)b * SC_ + slot) * heads + h) * HD_ + d] = __float2half_rn(r);
    } else {
        ((float*)qkv)[in_idx] = r;
    }
}

// ---------------- fp16 tensor-core flash attention ------------------------------------
#define QKH 264    // Q/K smem row stride (halves)
#define VTS 40     // Vt / Ph row stride (halves)
#define SSS 36     // Ss fp32 row stride

struct AttnSmemH {
    __half Qhi[32 * QKH];
    __half Qlo[32 * QKH];
    __half Kh [32 * QKH];
    __half Vt [256 * VTS];
    __half Ph [32 * VTS];
    float  Ss [32 * SSS];
    float m[32], l[32], al[32];
    int   pos[32];
    int   srange[2];
};

__global__ void __launch_bounds__(256, 2) attn_f16(const int* __restrict__ seg)
{
    extern __shared__ char smem_raw[];
    AttnSmemH& sm = *reinterpret_cast<AttnSmemH*>(smem_raw);

    const int tid  = threadIdx.x;
    const int warp = tid >> 5;
    const int lane = tid & 31;
    const int gid  = lane >> 2;
    const int tig  = lane & 3;
    const int warpM = warp >> 2;
    const int warpN = warp & 3;

    const int q0 = blockIdx.x * 32;
    const int h  = blockIdx.y;
    const int b  = blockIdx.z;
    const int kvh = h / (NH_ / NKV_);

    const float* qbase = g_qkv + ((size_t)b * T_ + q0) * QKVW + h * HD_;
    const float qscale = 0.0625f;
#pragma unroll
    for (int j = 0; j < 8; j++) {
        const int fi = tid + j * 256;
        const int r = fi >> 6, c4 = (fi & 63) * 4;
        float4 v = *(const float4*)(qbase + (size_t)r * QKVW + c4);
        __half h0, l0, h1, l1, h2, l2, h3, l3;
        f16split(v.x * qscale, h0, l0);
        f16split(v.y * qscale, h1, l1);
        f16split(v.z * qscale, h2, l2);
        f16split(v.w * qscale, h3, l3);
        *(half2*)&sm.Qhi[r*QKH + c4]     = __halves2half2(h0, h1);
        *(half2*)&sm.Qhi[r*QKH + c4 + 2] = __halves2half2(h2, h3);
        *(half2*)&sm.Qlo[r*QKH + c4]     = __halves2half2(l0, l1);
        *(half2*)&sm.Qlo[r*QKH + c4 + 2] = __halves2half2(l2, l3);
    }
    if (tid < 32) {
        sm.m[tid] = -1e30f;
        sm.l[tid] = 0.0f;
        sm.pos[tid] = seg[b * T_ + q0 + tid];
    }
    __syncthreads();
    if (tid == 0) {
        int mn = sm.pos[0], mx = sm.pos[0];
        for (int j = 1; j < 32; j++) { mn = min(mn, sm.pos[j]); mx = max(mx, sm.pos[j]); }
        int lo = mn - (WIN_ - 1); if (lo < 0) lo = 0;
        int hi = mx; if (hi > SC_ - 1) hi = SC_ - 1;
        sm.srange[0] = lo & ~31;
        sm.srange[1] = hi;
    }
    __syncthreads();
    const int s_lo = sm.srange[0], s_hi = sm.srange[1];

    const int arow = warpM * 16 + gid;

    float o[8][4];
#pragma unroll
    for (int nf = 0; nf < 8; nf++)
#pragma unroll
        for (int r = 0; r < 4; r++) o[nf][r] = 0.0f;

    const __half* khbase = g_kch + ((size_t)b * SC_ * NKV_ + kvh) * HD_;
    const __half* vtbase = g_vct + (size_t)(b * NKV_ + kvh) * HD_ * SC_;

    for (int s0 = s_lo; s0 <= s_hi; s0 += 32) {
        // ---- K + V tiles ----
#pragma unroll
        for (int j = 0; j < 4; j++) {
            const int fi = tid + j * 256;
            const int r = fi >> 5, c8 = (fi & 31) * 8;
            *(uint4*)&sm.Kh[r*QKH + c8] =
                *(const uint4*)(khbase + (size_t)(s0 + r) * NKV_ * HD_ + c8);
        }
#pragma unroll
        for (int j = 0; j < 4; j++) {
            const int fi = tid + j * 256;
            const int d = fi >> 2, c8 = (fi & 3) * 8;
            *(uint4*)&sm.Vt[d*VTS + c8] =
                *(const uint4*)(vtbase + (size_t)d * SC_ + s0 + c8);
        }
        __syncthreads();

        // ---- QK^T: 2 mma per k16 (q-side split only) ----
        float sc0 = 0.f, sc1 = 0.f, sc2 = 0.f, sc3 = 0.f;
        const int bcol = warpN * 8 + gid;
#pragma unroll
        for (int kb = 0; kb < HD_; kb += 16) {
            const uint32_t qh0 = *(const uint32_t*)&sm.Qhi[(arow)    *QKH + kb + tig*2];
            const uint32_t qh1 = *(const uint32_t*)&sm.Qhi[(arow + 8)*QKH + kb + tig*2];
            const uint32_t qh2 = *(const uint32_t*)&sm.Qhi[(arow)    *QKH + kb + 8 + tig*2];
            const uint32_t qh3 = *(const uint32_t*)&sm.Qhi[(arow + 8)*QKH + kb + 8 + tig*2];
            const uint32_t ql0 = *(const uint32_t*)&sm.Qlo[(arow)    *QKH + kb + tig*2];
            const uint32_t ql1 = *(const uint32_t*)&sm.Qlo[(arow + 8)*QKH + kb + tig*2];
            const uint32_t ql2 = *(const uint32_t*)&sm.Qlo[(arow)    *QKH + kb + 8 + tig*2];
            const uint32_t ql3 = *(const uint32_t*)&sm.Qlo[(arow + 8)*QKH + kb + 8 + tig*2];
            const uint32_t k0 = *(const uint32_t*)&sm.Kh[bcol*QKH + kb + tig*2];
            const uint32_t k1 = *(const uint32_t*)&sm.Kh[bcol*QKH + kb + 8 + tig*2];
            mma_f16(sc0, sc1, sc2, sc3, qh0, qh1, qh2, qh3, k0, k1);
            mma_f16(sc0, sc1, sc2, sc3, ql0, ql1, ql2, ql3, k0, k1);
        }

        // ---- softcap + mask ----
        {
            const int c0 = warpN * 8 + tig * 2;
            const int sa = s0 + c0, sb2 = s0 + c0 + 1;
            const int qp0 = sm.pos[arow], qp1 = sm.pos[arow + 8];
            const float v0 = SOFTCAP * fast_tanh(sc0 * (1.0f / SOFTCAP));
            const float v1 = SOFTCAP * fast_tanh(sc1 * (1.0f / SOFTCAP));
            const float v2 = SOFTCAP * fast_tanh(sc2 * (1.0f / SOFTCAP));
            const float v3 = SOFTCAP * fast_tanh(sc3 * (1.0f / SOFTCAP));
            sm.Ss[(arow)    *SSS + c0    ] = (sa  <= qp0 && qp0 - sa  < WIN_) ? v0 : NEGINF;
            sm.Ss[(arow)    *SSS + c0 + 1] = (sb2 <= qp0 && qp0 - sb2 < WIN_) ? v1 : NEGINF;
            sm.Ss[(arow + 8)*SSS + c0    ] = (sa  <= qp1 && qp1 - sa  < WIN_) ? v2 : NEGINF;
            sm.Ss[(arow + 8)*SSS + c0 + 1] = (sb2 <= qp1 && qp1 - sb2 < WIN_) ? v3 : NEGINF;
        }
        __syncthreads();

        // ---- online softmax; P as fp16 ----
        {
            const int r = tid >> 3, sub = tid & 7;
            const float* srow = &sm.Ss[r * SSS + sub * 4];
            float mx = fmaxf(fmaxf(srow[0], srow[1]), fmaxf(srow[2], srow[3]));
#pragma unroll
            for (int off = 1; off < 8; off <<= 1)
                mx = fmaxf(mx, __shfl_xor_sync(0xffffffffu, mx, off));
            const float mo = sm.m[r];
            const float mn = fmaxf(mo, mx);
            const float a  = __expf(mo - mn);
            const float p0 = __expf(srow[0] - mn);
            const float p1 = __expf(srow[1] - mn);
            const float p2 = __expf(srow[2] - mn);
            const float p3 = __expf(srow[3] - mn);
            float ls = p0 + p1 + p2 + p3;
            *(half2*)&sm.Ph[r * VTS + sub * 4]     = __floats2half2_rn(p0, p1);
            *(half2*)&sm.Ph[r * VTS + sub * 4 + 2] = __floats2half2_rn(p2, p3);
#pragma unroll
            for (int off = 1; off < 8; off <<= 1)
                ls += __shfl_xor_sync(0xffffffffu, ls, off);
            if (sub == 0) {
                sm.m[r] = mn;
                sm.l[r] = sm.l[r] * a + ls;
                sm.al[r] = a;
            }
        }
        __syncthreads();

        // ---- P @ V ----
        {
            const float a0 = sm.al[arow], a1 = sm.al[arow + 8];
#pragma unroll
            for (int nf = 0; nf < 8; nf++) {
                o[nf][0] *= a0; o[nf][1] *= a0;
                o[nf][2] *= a1; o[nf][3] *= a1;
            }
#pragma unroll
            for (int kb = 0; kb < 32; kb += 16) {
                const uint32_t pa0 = *(const uint32_t*)&sm.Ph[(arow)    *VTS + kb + tig*2];
                const uint32_t pa1 = *(const uint32_t*)&sm.Ph[(arow + 8)*VTS + kb + tig*2];
                const uint32_t pa2 = *(const uint32_t*)&sm.Ph[(arow)    *VTS + kb + 8 + tig*2];
                const uint32_t pa3 = *(const uint32_t*)&sm.Ph[(arow + 8)*VTS + kb + 8 + tig*2];
#pragma unroll
                for (int nf = 0; nf < 8; nf++) {
                    const int col = warpN * 64 + nf * 8 + gid;
                    const uint32_t b0 = *(const uint32_t*)&sm.Vt[col*VTS + kb + tig*2];
                    const uint32_t b1 = *(const uint32_t*)&sm.Vt[col*VTS + kb + 8 + tig*2];
                    mma_f16(o[nf][0], o[nf][1], o[nf][2], o[nf][3],
                            pa0, pa1, pa2, pa3, b0, b1);
                }
            }
        }
        __syncthreads();
    }

    const float li0 = 1.0f / sm.l[arow];
    const float li1 = 1.0f / sm.l[arow + 8];
    const int row0g = q0 + arow;
#pragma unroll
    for (int nf = 0; nf < 8; nf++) {
        const int col = warpN * 64 + nf * 8 + tig * 2;
        __half* p0 = g_attn + (((size_t)b * T_ + row0g)     * NH_ + h) * HD_ + col;
        __half* p1 = g_attn + (((size_t)b * T_ + row0g + 8) * NH_ + h) * HD_ + col;
        *(half2*)p0 = __floats2half2_rn(o[nf][0] * li0, o[nf][1] * li0);
        *(half2*)p1 = __floats2half2_rn(o[nf][2] * li1, o[nf][3] * li1);
    }
}

// ---------------- launcher ----------------------------------------------------------
extern "C" void kernel_launch(void* const* d_in, const int* in_sizes, int n_in,
                              void* d_out, int out_size)
{
    const float* x      = (const float*)d_in[0];
    const int*   seg    = (const int*)  d_in[1];
    const int*   cur    = (const int*)  d_in[2];
    const float* wq     = (const float*)d_in[3];
    const float* wk     = (const float*)d_in[4];
    const float* wv     = (const float*)d_in[5];
    const float* wo     = (const float*)d_in[6];
    const float* qns    = (const float*)d_in[7];
    const float* kns    = (const float*)d_in[8];
    const float* kcache = (const float*)d_in[9];
    const float* vcache = (const float*)d_in[10];
    float* out = (float*)d_out;

    float *qkvp;
    __half *xh, *wqkvT, *woT, *attnp;
    cudaGetSymbolAddress((void**)&qkvp,  g_qkv);
    cudaGetSymbolAddress((void**)&xh,    g_xh);
    cudaGetSymbolAddress((void**)&wqkvT, g_wqkvT);
    cudaGetSymbolAddress((void**)&woT,   g_woT);
    cudaGetSymbolAddress((void**)&attnp, g_attn);

    const int M = B_ * T_;

    // preprocessing
    f2h<<<((B_*T_*D_/4) + 255)/256, 256>>>(x, xh, B_*T_*D_/4);
    wtrans_h<<<dim3(2048/32, D_/32), dim3(32,8)>>>(wq, wqkvT,                   D_, 2048);
    wtrans_h<<<dim3(1024/32, D_/32), dim3(32,8)>>>(wk, wqkvT + (size_t)2048*D_, D_, 1024);
    wtrans_h<<<dim3(1024/32, D_/32), dim3(32,8)>>>(wv, wqkvT + (size_t)3072*D_, D_, 1024);
    wtrans_h<<<dim3(D_/32, (NH_*HD_)/32), dim3(32,8)>>>(wo, woT, NH_*HD_, D_);

    rope_table_kernel<<<(SC_ * 128) / 256, 256>>>();

    cudaFuncSetAttribute(gemm_f16, cudaFuncAttributeMaxDynamicSharedMemorySize, GSMEM);

    // fused QKV projection
    gemm_f16<<<dim3(QKVW/128, M/128), 256, GSMEM>>>(xh, wqkvT, qkvp, M, QKVW, D_);

    // caches
    merge_k<<<(B_*SC_*NKV_*HD_/4)/256, 256>>>(kcache);
    vtrans_cache<<<dim3(SC_/32, HD_/32, B_*NKV_), dim3(32,8)>>>(vcache, cur);

    normrope_kernel<<<dim3(M, NH_),  256>>>(qkvp, qns, seg, cur, NH_,  0,    0);
    normrope_kernel<<<dim3(M, NKV_), 256>>>(qkvp, kns, seg, cur, NKV_, 2048, 1);

    cudaFuncSetAttribute(attn_f16, cudaFuncAttributeMaxDynamicSharedMemorySize,
                         (int)sizeof(AttnSmemH));
    attn_f16<<<dim3(T_/32, NH_, B_), 256, sizeof(AttnSmemH)>>>(seg);

    // output projection
    gemm_f16<<<dim3(D_/128, M/128), 256, GSMEM>>>(attnp, woT, out, M, D_, NH_*HD_);
}

// round 12
// speedup vs baseline: 2.0670x; 1.0476x over previous
#include <cuda_runtime.h>
#include <cuda_fp16.h>
#include <math.h>
#include <stdint.h>

#define B_      2
#define T_      2048
#define D_      2048
#define NH_     8
#define NKV_    4
#define HD_     256
#define SC_     2048
#define WIN_    512
#define SOFTCAP 50.0f
#define NEGINF  -2.3819763e38f
#define QKVW    4096

// ---------------- scratch (device globals; no allocation allowed) ------------
__device__ float  g_qkv[(size_t)B_*T_*QKVW];         // fp32 q|k|v
__device__ __half g_xh[(size_t)B_*T_*D_];            // fp16 x
__device__ __half g_wqkvT[(size_t)QKVW*D_];          // fp16 [N=4096][K=2048]
__device__ __half g_woT[(size_t)D_*(NH_*HD_)];       // fp16 [N=2048][K=2048]
__device__ __half g_attn[(size_t)B_*T_*NH_*HD_];     // fp16 attention output
__device__ __half g_kch[(size_t)B_*SC_*NKV_*HD_];    // K cache (fp16)
__device__ __half g_vct[(size_t)B_*NKV_*HD_*SC_];    // V cache transposed [b][kv][d][s]
__device__ float2 g_rope[(size_t)SC_*128];

// ---------------- helpers -------------------------------------------------------
__device__ __forceinline__ void f16split(float x, __half& hi, __half& lo) {
    hi = __float2half_rn(x);
    lo = __float2half_rn(x - __half2float(hi));
}

__device__ __forceinline__ void mma_f16(float& d0, float& d1, float& d2, float& d3,
                                        uint32_t a0, uint32_t a1, uint32_t a2, uint32_t a3,
                                        uint32_t b0, uint32_t b1) {
    asm volatile("mma.sync.aligned.m16n8k16.row.col.f32.f16.f16.f32 "
                 "{%0,%1,%2,%3}, {%4,%5,%6,%7}, {%8,%9}, {%0,%1,%2,%3};"
                 : "+f"(d0), "+f"(d1), "+f"(d2), "+f"(d3)
                 : "r"(a0), "r"(a1), "r"(a2), "r"(a3), "r"(b0), "r"(b1));
}

__device__ __forceinline__ void ldmatrix_x4(uint32_t& r0, uint32_t& r1,
                                            uint32_t& r2, uint32_t& r3, uint32_t saddr) {
    asm volatile("ldmatrix.sync.aligned.m8n8.x4.shared.b16 {%0,%1,%2,%3}, [%4];"
                 : "=r"(r0), "=r"(r1), "=r"(r2), "=r"(r3) : "r"(saddr));
}

__device__ __forceinline__ void cpasync16(uint32_t saddr, const void* gptr) {
    asm volatile("cp.async.cg.shared.global [%0], [%1], 16;\n" :: "r"(saddr), "l"(gptr));
}
__device__ __forceinline__ void cpasync_commit() { asm volatile("cp.async.commit_group;"); }
__device__ __forceinline__ void cpasync_wait0()  { asm volatile("cp.async.wait_group 0;"); }
__device__ __forceinline__ void cpasync_wait1()  { asm volatile("cp.async.wait_group 1;"); }

__device__ __forceinline__ float fast_tanh(float x) {
    float xc = fminf(fmaxf(x, -15.0f), 15.0f);
    float e = __expf(-2.0f * xc);
    return (1.0f - e) / (1.0f + e);
}

// ---------------- preprocessing ---------------------------------------------------
__global__ void f2h(const float* __restrict__ in, __half* __restrict__ out, int n4)
{
    const int i = blockIdx.x * 256 + threadIdx.x;
    if (i < n4) {
        float4 v = ((const float4*)in)[i];
        half2 h0 = __floats2half2_rn(v.x, v.y);
        half2 h1 = __floats2half2_rn(v.z, v.w);
        half2* dst = (half2*)(out + (size_t)i * 4);
        dst[0] = h0; dst[1] = h1;
    }
}

// w[K][N] fp32 -> wt[N][K] fp16
__global__ void wtrans_h(const float* __restrict__ w, __half* __restrict__ wt, int K, int N)
{
    __shared__ float tile[32][33];
    const int n0 = blockIdx.x * 32, k0 = blockIdx.y * 32;
    const int tx = threadIdx.x, ty = threadIdx.y;
#pragma unroll
    for (int i = 0; i < 32; i += 8)
        tile[ty + i][tx] = w[(size_t)(k0 + ty + i) * N + n0 + tx];
    __syncthreads();
#pragma unroll
    for (int i = 0; i < 32; i += 8)
        wt[(size_t)(n0 + ty + i) * K + k0 + tx] = __float2half_rn(tile[tx][ty + i]);
}

// ---------------- fp16 tensor-core GEMM: BK=32, 3-stage, ldmatrix fragments --------
#define AST2 40                       // smem row stride (halves): 20 words, conflict-free
#define STG2 (128 * AST2)
#define GSMEM (3 * 2 * STG2 * 2)      // 61440 B

__global__ void __launch_bounds__(256) gemm_f16(const __half* __restrict__ A,
                                                const __half* __restrict__ Bt,
                                                float* __restrict__ C,
                                                int M, int N, int K)
{
    extern __shared__ __half hs[];
    __half* As = hs;                  // [3][STG2]
    __half* Bs = hs + 3 * STG2;       // [3][STG2]

    const int tid  = threadIdx.x;
    const int warp = tid >> 5;
    const int lane = tid & 31;
    const int warpM = warp >> 2;
    const int warpN = warp & 3;
    const int gid = lane >> 2;
    const int tig = lane & 3;

    const int row0 = blockIdx.y * 128;
    const int col0 = blockIdx.x * 128;

    uint32_t sA = (uint32_t)__cvta_generic_to_shared(As);
    uint32_t sB = (uint32_t)__cvta_generic_to_shared(Bs);

    const int ld_r = tid >> 1;
    const int ld_c = (tid & 1) * 2;

    // ldmatrix per-lane address components
    const int a_lrow   = lane & 15;
    const int a_lchunk = (lane >> 4) * 8;
    const int b_lrow   = (lane & 7) + ((lane >> 4) << 3);
    const int b_lchunk = ((lane >> 3) & 1) * 8;

    const int ntiles = K / 32;

    auto load_tile = [&](int kt, int st) {
#pragma unroll
        for (int c = 0; c < 2; c++) {
            cpasync16(sA + (uint32_t)(st * STG2 + ld_r * AST2) * 2 + (ld_c + c) * 16,
                      A + (size_t)(row0 + ld_r) * K + kt * 32 + (ld_c + c) * 8);
            cpasync16(sB + (uint32_t)(st * STG2 + ld_r * AST2) * 2 + (ld_c + c) * 16,
                      Bt + (size_t)(col0 + ld_r) * K + kt * 32 + (ld_c + c) * 8);
        }
    };

    float acc[4][4][4];
#pragma unroll
    for (int i = 0; i < 4; i++)
#pragma unroll
        for (int j = 0; j < 4; j++)
#pragma unroll
            for (int r = 0; r < 4; r++) acc[i][j][r] = 0.0f;

    load_tile(0, 0);
    cpasync_commit();
    load_tile(1, 1);
    cpasync_commit();

    for (int kt = 0; kt < ntiles; kt++) {
        const int st = kt % 3;
        if (kt + 1 < ntiles) cpasync_wait1(); else cpasync_wait0();
        __syncthreads();

        const uint32_t sAst = sA + (uint32_t)(st * STG2) * 2;
        const uint32_t sBst = sB + (uint32_t)(st * STG2) * 2;

#pragma unroll
        for (int ks = 0; ks < 2; ks++) {
            const int kb = ks * 16;
            uint32_t bf[4][2];
#pragma unroll
            for (int p = 0; p < 2; p++) {
                const uint32_t baddr = sBst +
                    (uint32_t)((warpN * 32 + p * 16 + b_lrow) * AST2 + kb + b_lchunk) * 2;
                ldmatrix_x4(bf[2*p][0], bf[2*p][1], bf[2*p+1][0], bf[2*p+1][1], baddr);
            }
#pragma unroll
            for (int mt = 0; mt < 4; mt++) {
                const int rb = warpM * 64 + mt * 16;
                uint32_t a0, a1, a2, a3;
                const uint32_t aaddr = sAst +
                    (uint32_t)((rb + a_lrow) * AST2 + kb + a_lchunk) * 2;
                ldmatrix_x4(a0, a1, a2, a3, aaddr);
#pragma unroll
                for (int nt = 0; nt < 4; nt++)
                    mma_f16(acc[mt][nt][0], acc[mt][nt][1], acc[mt][nt][2], acc[mt][nt][3],
                            a0, a1, a2, a3, bf[nt][0], bf[nt][1]);
            }
        }

        if (kt + 2 < ntiles) {
            load_tile(kt + 2, (kt + 2) % 3);
            cpasync_commit();
        }
    }

#pragma unroll
    for (int mt = 0; mt < 4; mt++) {
        const int r = row0 + warpM * 64 + mt * 16 + gid;
#pragma unroll
        for (int nt = 0; nt < 4; nt++) {
            const int c = col0 + warpN * 32 + nt * 8 + tig * 2;
            *(float2*)(C + (size_t)r * N + c)       = make_float2(acc[mt][nt][0], acc[mt][nt][1]);
            *(float2*)(C + (size_t)(r + 8) * N + c) = make_float2(acc[mt][nt][2], acc[mt][nt][3]);
        }
    }
}

// ---------------- rope table -------------------------------------------------------
__global__ void rope_table_kernel()
{
    const int idx = blockIdx.x * 256 + threadIdx.x;
    const int pos = idx >> 7;
    const int i   = idx & 127;
    const double ts  = pow(10000.0, (double)i / 128.0);
    const double ang = (double)pos / ts;
    double sn, cs;
    sincos(ang, &sn, &cs);
    g_rope[idx] = make_float2((float)cs, (float)sn);
}

// ---------------- K cache merge (fp16) -----------------------------------------------
__global__ void merge_k(const float* __restrict__ kcache)
{
    const int i = blockIdx.x * 256 + threadIdx.x;
    float4 v = ((const float4*)kcache)[i];
    half2* dst = (half2*)(g_kch + (size_t)i * 4);
    dst[0] = __floats2half2_rn(v.x, v.y);
    dst[1] = __floats2half2_rn(v.z, v.w);
}

// ---------------- V cache: select + transpose + fp16 ----------------------------------
__global__ void vtrans_cache(const float* __restrict__ vcache, const int* __restrict__ cur)
{
    __shared__ float tile[32][33];
    const int s0 = blockIdx.x * 32, d0 = blockIdx.y * 32;
    const int bk = blockIdx.z;
    const int b = bk / NKV_, kv = bk % NKV_;
    const int tx = threadIdx.x, ty = threadIdx.y;
    const int ci = *cur;
#pragma unroll
    for (int i = 0; i < 32; i += 8) {
        const int s = s0 + ty + i;
        const int t = s - ci;
        const float v = (t >= 0 && t < T_)
            ? g_qkv[((size_t)b * T_ + t) * QKVW + 3072 + kv * HD_ + d0 + tx]
            : vcache[(((size_t)b * SC_ + s) * NKV_ + kv) * HD_ + d0 + tx];
        tile[ty + i][tx] = v;
    }
    __syncthreads();
#pragma unroll
    for (int i = 0; i < 32; i += 8) {
        const int d = d0 + ty + i;
        g_vct[((size_t)(b * NKV_ + kv) * HD_ + d) * SC_ + s0 + tx] =
            __float2half_rn(tile[tx][ty + i]);
    }
}

// ---------------- RMSNorm + RoPE ------------------------------------------------------
__global__ void normrope_kernel(const float* __restrict__ qkv,
                                const float* __restrict__ scale,
                                const int* __restrict__ seg,
                                const int* __restrict__ cur,
                                int heads, int in_off, int to_cache)
{
    const int bt = blockIdx.x;
    const int h  = blockIdx.y;
    const int d  = threadIdx.x;

    const size_t in_idx = (size_t)bt * QKVW + in_off + h * HD_ + d;
    const float v = qkv[in_idx];

    float ss = v * v;
#pragma unroll
    for (int o = 16; o; o >>= 1) ss += __shfl_xor_sync(0xffffffffu, ss, o);
    __shared__ float red[8];
    __shared__ float s_ms;
    __shared__ float sh[HD_];
    const int lane = d & 31, w = d >> 5;
    if (lane == 0) red[w] = ss;
    __syncthreads();
    if (d == 0) {
        float t = 0.0f;
#pragma unroll
        for (int i = 0; i < 8; i++) t += red[i];
        s_ms = rsqrtf(t / (float)HD_ + 1e-6f);
    }
    __syncthreads();

    const float n = v * s_ms * (1.0f + scale[d]);
    sh[d] = n;
    __syncthreads();

    int pos = seg[bt];
    if (pos < 0) pos = 0;
    if (pos > SC_ - 1) pos = SC_ - 1;
    const int i = d & 127;
    const float2 cssn = g_rope[pos * 128 + i];
    const float x1 = sh[i], x2 = sh[i + 128];
    const float r = (d < 128) ? (x1 * cssn.x - x2 * cssn.y)
                              : (x2 * cssn.x + x1 * cssn.y);

    if (to_cache) {
        const int b = bt / T_, t = bt - b * T_;
        const int slot = *cur + t;
        if (slot < SC_)
            g_kch[(((size_t)b * SC_ + slot) * heads + h) * HD_ + d] = __float2half_rn(r);
    } else {
        ((float*)qkv)[in_idx] = r;
    }
}

// ---------------- fp16 tensor-core flash attention ------------------------------------
#define QKH 264
#define VTS 40
#define SSS 36

struct AttnSmemH {
    __half Qhi[32 * QKH];
    __half Qlo[32 * QKH];
    __half Kh [32 * QKH];
    __half Vt [256 * VTS];
    __half Ph [32 * VTS];
    float  Ss [32 * SSS];
    float m[32], l[32], al[32];
    int   pos[32];
    int   srange[2];
};

__global__ void __launch_bounds__(256, 2) attn_f16(const int* __restrict__ seg)
{
    extern __shared__ char smem_raw[];
    AttnSmemH& sm = *reinterpret_cast<AttnSmemH*>(smem_raw);

    const int tid  = threadIdx.x;
    const int warp = tid >> 5;
    const int lane = tid & 31;
    const int gid  = lane >> 2;
    const int tig  = lane & 3;
    const int warpM = warp >> 2;
    const int warpN = warp & 3;

    const int q0 = blockIdx.x * 32;
    const int h  = blockIdx.y;
    const int b  = blockIdx.z;
    const int kvh = h / (NH_ / NKV_);

    const float* qbase = g_qkv + ((size_t)b * T_ + q0) * QKVW + h * HD_;
    const float qscale = 0.0625f;
#pragma unroll
    for (int j = 0; j < 8; j++) {
        const int fi = tid + j * 256;
        const int r = fi >> 6, c4 = (fi & 63) * 4;
        float4 v = *(const float4*)(qbase + (size_t)r * QKVW + c4);
        __half h0, l0, h1, l1, h2, l2, h3, l3;
        f16split(v.x * qscale, h0, l0);
        f16split(v.y * qscale, h1, l1);
        f16split(v.z * qscale, h2, l2);
        f16split(v.w * qscale, h3, l3);
        *(half2*)&sm.Qhi[r*QKH + c4]     = __halves2half2(h0, h1);
        *(half2*)&sm.Qhi[r*QKH + c4 + 2] = __halves2half2(h2, h3);
        *(half2*)&sm.Qlo[r*QKH + c4]     = __halves2half2(l0, l1);
        *(half2*)&sm.Qlo[r*QKH + c4 + 2] = __halves2half2(l2, l3);
    }
    if (tid < 32) {
        sm.m[tid] = -1e30f;
        sm.l[tid] = 0.0f;
        sm.pos[tid] = seg[b * T_ + q0 + tid];
    }
    __syncthreads();
    if (tid == 0) {
        int mn = sm.pos[0], mx = sm.pos[0];
        for (int j = 1; j < 32; j++) { mn = min(mn, sm.pos[j]); mx = max(mx, sm.pos[j]); }
        int lo = mn - (WIN_ - 1); if (lo < 0) lo = 0;
        int hi = mx; if (hi > SC_ - 1) hi = SC_ - 1;
        sm.srange[0] = lo & ~31;
        sm.srange[1] = hi;
    }
    __syncthreads();
    const int s_lo = sm.srange[0], s_hi = sm.srange[1];

    const int arow = warpM * 16 + gid;

    float o[8][4];
#pragma unroll
    for (int nf = 0; nf < 8; nf++)
#pragma unroll
        for (int r = 0; r < 4; r++) o[nf][r] = 0.0f;

    const __half* khbase = g_kch + ((size_t)b * SC_ * NKV_ + kvh) * HD_;
    const __half* vtbase = g_vct + (size_t)(b * NKV_ + kvh) * HD_ * SC_;

    for (int s0 = s_lo; s0 <= s_hi; s0 += 32) {
#pragma unroll
        for (int j = 0; j < 4; j++) {
            const int fi = tid + j * 256;
            const int r = fi >> 5, c8 = (fi & 31) * 8;
            *(uint4*)&sm.Kh[r*QKH + c8] =
                *(const uint4*)(khbase + (size_t)(s0 + r) * NKV_ * HD_ + c8);
        }
#pragma unroll
        for (int j = 0; j < 4; j++) {
            const int fi = tid + j * 256;
            const int d = fi >> 2, c8 = (fi & 3) * 8;
            *(uint4*)&sm.Vt[d*VTS + c8] =
                *(const uint4*)(vtbase + (size_t)d * SC_ + s0 + c8);
        }
        __syncthreads();

        float sc0 = 0.f, sc1 = 0.f, sc2 = 0.f, sc3 = 0.f;
        const int bcol = warpN * 8 + gid;
#pragma unroll
        for (int kb = 0; kb < HD_; kb += 16) {
            const uint32_t qh0 = *(const uint32_t*)&sm.Qhi[(arow)    *QKH + kb + tig*2];
            const uint32_t qh1 = *(const uint32_t*)&sm.Qhi[(arow + 8)*QKH + kb + tig*2];
            const uint32_t qh2 = *(const uint32_t*)&sm.Qhi[(arow)    *QKH + kb + 8 + tig*2];
            const uint32_t qh3 = *(const uint32_t*)&sm.Qhi[(arow + 8)*QKH + kb + 8 + tig*2];
            const uint32_t ql0 = *(const uint32_t*)&sm.Qlo[(arow)    *QKH + kb + tig*2];
            const uint32_t ql1 = *(const uint32_t*)&sm.Qlo[(arow + 8)*QKH + kb + tig*2];
            const uint32_t ql2 = *(const uint32_t*)&sm.Qlo[(arow)    *QKH + kb + 8 + tig*2];
            const uint32_t ql3 = *(const uint32_t*)&sm.Qlo[(arow + 8)*QKH + kb + 8 + tig*2];
            const uint32_t k0 = *(const uint32_t*)&sm.Kh[bcol*QKH + kb + tig*2];
            const uint32_t k1 = *(const uint32_t*)&sm.Kh[bcol*QKH + kb + 8 + tig*2];
            mma_f16(sc0, sc1, sc2, sc3, qh0, qh1, qh2, qh3, k0, k1);
            mma_f16(sc0, sc1, sc2, sc3, ql0, ql1, ql2, ql3, k0, k1);
        }

        {
            const int c0 = warpN * 8 + tig * 2;
            const int sa = s0 + c0, sb2 = s0 + c0 + 1;
            const int qp0 = sm.pos[arow], qp1 = sm.pos[arow + 8];
            const float v0 = SOFTCAP * fast_tanh(sc0 * (1.0f / SOFTCAP));
            const float v1 = SOFTCAP * fast_tanh(sc1 * (1.0f / SOFTCAP));
            const float v2 = SOFTCAP * fast_tanh(sc2 * (1.0f / SOFTCAP));
            const float v3 = SOFTCAP * fast_tanh(sc3 * (1.0f / SOFTCAP));
            sm.Ss[(arow)    *SSS + c0    ] = (sa  <= qp0 && qp0 - sa  < WIN_) ? v0 : NEGINF;
            sm.Ss[(arow)    *SSS + c0 + 1] = (sb2 <= qp0 && qp0 - sb2 < WIN_) ? v1 : NEGINF;
            sm.Ss[(arow + 8)*SSS + c0    ] = (sa  <= qp1 && qp1 - sa  < WIN_) ? v2 : NEGINF;
            sm.Ss[(arow + 8)*SSS + c0 + 1] = (sb2 <= qp1 && qp1 - sb2 < WIN_) ? v3 : NEGINF;
        }
        __syncthreads();

        {
            const int r = tid >> 3, sub = tid & 7;
            const float* srow = &sm.Ss[r * SSS + sub * 4];
            float mx = fmaxf(fmaxf(srow[0], srow[1]), fmaxf(srow[2], srow[3]));
#pragma unroll
            for (int off = 1; off < 8; off <<= 1)
                mx = fmaxf(mx, __shfl_xor_sync(0xffffffffu, mx, off));
            const float mo = sm.m[r];
            const float mn = fmaxf(mo, mx);
            const float a  = __expf(mo - mn);
            const float p0 = __expf(srow[0] - mn);
            const float p1 = __expf(srow[1] - mn);
            const float p2 = __expf(srow[2] - mn);
            const float p3 = __expf(srow[3] - mn);
            float ls = p0 + p1 + p2 + p3;
            *(half2*)&sm.Ph[r * VTS + sub * 4]     = __floats2half2_rn(p0, p1);
            *(half2*)&sm.Ph[r * VTS + sub * 4 + 2] = __floats2half2_rn(p2, p3);
#pragma unroll
            for (int off = 1; off < 8; off <<= 1)
                ls += __shfl_xor_sync(0xffffffffu, ls, off);
            if (sub == 0) {
                sm.m[r] = mn;
                sm.l[r] = sm.l[r] * a + ls;
                sm.al[r] = a;
            }
        }
        __syncthreads();

        {
            const float a0 = sm.al[arow], a1 = sm.al[arow + 8];
#pragma unroll
            for (int nf = 0; nf < 8; nf++) {
                o[nf][0] *= a0; o[nf][1] *= a0;
                o[nf][2] *= a1; o[nf][3] *= a1;
            }
#pragma unroll
            for (int kb = 0; kb < 32; kb += 16) {
                const uint32_t pa0 = *(const uint32_t*)&sm.Ph[(arow)    *VTS + kb + tig*2];
                const uint32_t pa1 = *(const uint32_t*)&sm.Ph[(arow + 8)*VTS + kb + tig*2];
                const uint32_t pa2 = *(const uint32_t*)&sm.Ph[(arow)    *VTS + kb + 8 + tig*2];
                const uint32_t pa3 = *(const uint32_t*)&sm.Ph[(arow + 8)*VTS + kb + 8 + tig*2];
#pragma unroll
                for (int nf = 0; nf < 8; nf++) {
                    const int col = warpN * 64 + nf * 8 + gid;
                    const uint32_t b0 = *(const uint32_t*)&sm.Vt[col*VTS + kb + tig*2];
                    const uint32_t b1 = *(const uint32_t*)&sm.Vt[col*VTS + kb + 8 + tig*2];
                    mma_f16(o[nf][0], o[nf][1], o[nf][2], o[nf][3],
                            pa0, pa1, pa2, pa3, b0, b1);
                }
            }
        }
        __syncthreads();
    }

    const float li0 = 1.0f / sm.l[arow];
    const float li1 = 1.0f / sm.l[arow + 8];
    const int row0g = q0 + arow;
#pragma unroll
    for (int nf = 0; nf < 8; nf++) {
        const int col = warpN * 64 + nf * 8 + tig * 2;
        __half* p0 = g_attn + (((size_t)b * T_ + row0g)     * NH_ + h) * HD_ + col;
        __half* p1 = g_attn + (((size_t)b * T_ + row0g + 8) * NH_ + h) * HD_ + col;
        *(half2*)p0 = __floats2half2_rn(o[nf][0] * li0, o[nf][1] * li0);
        *(half2*)p1 = __floats2half2_rn(o[nf][2] * li1, o[nf][3] * li1);
    }
}

// ---------------- launcher ----------------------------------------------------------
extern "C" void kernel_launch(void* const* d_in, const int* in_sizes, int n_in,
                              void* d_out, int out_size)
{
    const float* x      = (const float*)d_in[0];
    const int*   seg    = (const int*)  d_in[1];
    const int*   cur    = (const int*)  d_in[2];
    const float* wq     = (const float*)d_in[3];
    const float* wk     = (const float*)d_in[4];
    const float* wv     = (const float*)d_in[5];
    const float* wo     = (const float*)d_in[6];
    const float* qns    = (const float*)d_in[7];
    const float* kns    = (const float*)d_in[8];
    const float* kcache = (const float*)d_in[9];
    const float* vcache = (const float*)d_in[10];
    float* out = (float*)d_out;

    float *qkvp;
    __half *xh, *wqkvT, *woT, *attnp;
    cudaGetSymbolAddress((void**)&qkvp,  g_qkv);
    cudaGetSymbolAddress((void**)&xh,    g_xh);
    cudaGetSymbolAddress((void**)&wqkvT, g_wqkvT);
    cudaGetSymbolAddress((void**)&woT,   g_woT);
    cudaGetSymbolAddress((void**)&attnp, g_attn);

    const int M = B_ * T_;

    // preprocessing
    f2h<<<((B_*T_*D_/4) + 255)/256, 256>>>(x, xh, B_*T_*D_/4);
    wtrans_h<<<dim3(2048/32, D_/32), dim3(32,8)>>>(wq, wqkvT,                   D_, 2048);
    wtrans_h<<<dim3(1024/32, D_/32), dim3(32,8)>>>(wk, wqkvT + (size_t)2048*D_, D_, 1024);
    wtrans_h<<<dim3(1024/32, D_/32), dim3(32,8)>>>(wv, wqkvT + (size_t)3072*D_, D_, 1024);
    wtrans_h<<<dim3(D_/32, (NH_*HD_)/32), dim3(32,8)>>>(wo, woT, NH_*HD_, D_);

    rope_table_kernel<<<(SC_ * 128) / 256, 256>>>();

    cudaFuncSetAttribute(gemm_f16, cudaFuncAttributeMaxDynamicSharedMemorySize, GSMEM);

    // fused QKV projection
    gemm_f16<<<dim3(QKVW/128, M/128), 256, GSMEM>>>(xh, wqkvT, qkvp, M, QKVW, D_);

    // caches
    merge_k<<<(B_*SC_*NKV_*HD_/4)/256, 256>>>(kcache);
    vtrans_cache<<<dim3(SC_/32, HD_/32, B_*NKV_), dim3(32,8)>>>(vcache, cur);

    normrope_kernel<<<dim3(M, NH_),  256>>>(qkvp, qns, seg, cur, NH_,  0,    0);
    normrope_kernel<<<dim3(M, NKV_), 256>>>(qkvp, kns, seg, cur, NKV_, 2048, 1);

    cudaFuncSetAttribute(attn_f16, cudaFuncAttributeMaxDynamicSharedMemorySize,
                         (int)sizeof(AttnSmemH));
    attn_f16<<<dim3(T_/32, NH_, B_), 256, sizeof(AttnSmemH)>>>(seg);

    // output projection
    gemm_f16<<<dim3(D_/128, M/128), 256, GSMEM>>>(attnp, woT, out, M, D_, NH_*HD_);
}